// round 12
// baseline (speedup 1.0000x reference)
#include <cuda_runtime.h>
#include <cuda_fp16.h>
#include <cstdint>
#include <math.h>

#define D_MODEL 4096
#define N_HEADS 16
#define D_HEAD  256
#define ROTARY  64
#define D_FF    16384
#define BATCH   2
#define SEQ     2048
#define NROWS   (BATCH*SEQ)   /* 4096 */
#define QKVW    12288         /* packed qkv row width */

#define STAGES 3
/* fp16 GEMM: BK=64 halfs, row stride 72 halfs = 144B (LDSM conflict-free) */
#define ROWB 144
#define STGB (128 * ROWB)          /* per-stage bytes per operand: 18,432 */
#define SMH  (STAGES * 2 * STGB)   /* 110,592 */
#define PERSIST_CTAS 296           /* 2 per SM x 148 SMs */

// ---------------------------------------------------------------------------
// Scratch (static device globals; no allocation allowed)
// ---------------------------------------------------------------------------
__device__ __align__(16) __half g_xn [(size_t)NROWS * D_MODEL];
__device__ __align__(16) __half g_xn2[(size_t)NROWS * D_MODEL];
__device__ __align__(16) __half g_qkv[(size_t)NROWS * QKVW];      // packed q|k|v
__device__ __align__(16) __half g_vt [(size_t)NROWS * D_MODEL];   // per-head V^T
__device__ __align__(16) __half g_ctx[(size_t)NROWS * D_MODEL];
__device__ __align__(16) __half g_h  [(size_t)NROWS * D_FF];
__device__ __align__(16) __half g_p  [(size_t)BATCH * N_HEADS * SEQ * SEQ]; // 256 MB probs
__device__ __align__(16) __half g_wh [(size_t)201326592];                   // 384 MB W^T fp16
__device__ __align__(16) float  g_x2 [(size_t)NROWS * D_MODEL];
__device__ __align__(16) float  g_sc [(size_t)BATCH * N_HEADS * SEQ * SEQ]; // 512 MB scores

// ---------------------------------------------------------------------------
// Helpers
// ---------------------------------------------------------------------------
__device__ __forceinline__ float gelu_f(float x) {
    return 0.5f * x * (1.0f + tanhf(0.7978845608028654f * (x + 0.044715f * x * x * x)));
}
__device__ __forceinline__ void cp16(uint32_t dst, const void* src) {
    asm volatile("cp.async.cg.shared.global [%0], [%1], 16;\n" :: "r"(dst), "l"(src));
}
__device__ __forceinline__ void cp_commit() {
    asm volatile("cp.async.commit_group;\n" ::: "memory");
}
__device__ __forceinline__ void cp_wait1() {
    asm volatile("cp.async.wait_group 1;\n" ::: "memory");
}
__device__ __forceinline__ void ldsm4(uint32_t& r0, uint32_t& r1, uint32_t& r2, uint32_t& r3,
                                      uint32_t addr) {
    asm volatile("ldmatrix.sync.aligned.m8n8.x4.shared.b16 {%0,%1,%2,%3}, [%4];"
                 : "=r"(r0), "=r"(r1), "=r"(r2), "=r"(r3) : "r"(addr));
}

// ---------------------------------------------------------------------------
// Weight transpose + fp16 convert: out[c][r] = half(in[r][c])
// ---------------------------------------------------------------------------
__global__ void transpose4_kernel(const float* __restrict__ w0, const float* __restrict__ w1,
                                  const float* __restrict__ w2, const float* __restrict__ w3,
                                  __half* __restrict__ o0, __half* __restrict__ o1,
                                  __half* __restrict__ o2, __half* __restrict__ o3)
{
    __shared__ float tile[32][33];
    const float* in; __half* out;
    switch (blockIdx.z) {
        case 0: in = w0; out = o0; break;
        case 1: in = w1; out = o1; break;
        case 2: in = w2; out = o2; break;
        default: in = w3; out = o3; break;
    }
    int x = blockIdx.x * 32 + threadIdx.x;
    int y = blockIdx.y * 32 + threadIdx.y;
#pragma unroll
    for (int j = 0; j < 32; j += 8)
        tile[threadIdx.y + j][threadIdx.x] = in[(size_t)(y + j) * 4096 + x];
    __syncthreads();
    x = blockIdx.y * 32 + threadIdx.x;
    y = blockIdx.x * 32 + threadIdx.y;
#pragma unroll
    for (int j = 0; j < 32; j += 8)
        out[(size_t)(y + j) * 4096 + x] = __float2half_rn(tile[threadIdx.x][threadIdx.y + j]);
}

__global__ void transpose_rc_kernel(const float* __restrict__ in, __half* __restrict__ out,
                                    int R, int C)
{
    __shared__ float tile[32][33];
    int x = blockIdx.x * 32 + threadIdx.x;
    int y = blockIdx.y * 32 + threadIdx.y;
#pragma unroll
    for (int j = 0; j < 32; j += 8)
        tile[threadIdx.y + j][threadIdx.x] = in[(size_t)(y + j) * C + x];
    __syncthreads();
    x = blockIdx.y * 32 + threadIdx.x;
    y = blockIdx.x * 32 + threadIdx.y;
#pragma unroll
    for (int j = 0; j < 32; j += 8)
        out[(size_t)(y + j) * R + x] = __float2half_rn(tile[threadIdx.x][threadIdx.y + j]);
}

// V (strided in qkv) -> Vt [(b*4096 + h*256 + d)][s] fp16 (k-contiguous per head)
__global__ void transpose_v_kernel(const __half* __restrict__ in, int ldin,
                                   __half* __restrict__ out)
{
    __shared__ __half tile[32][33];
    int x = blockIdx.x * 32 + threadIdx.x;    // dmodel col
    int y = blockIdx.y * 32 + threadIdx.y;    // bt row
#pragma unroll
    for (int j = 0; j < 32; j += 8)
        tile[threadIdx.y + j][threadIdx.x] = in[(size_t)(y + j) * ldin + x];
    __syncthreads();
    int d0 = blockIdx.x * 32 + threadIdx.y;   // dmodel index base
    int yo = blockIdx.y * 32 + threadIdx.x;   // bt index
    int b = yo >> 11, s = yo & (SEQ - 1);
#pragma unroll
    for (int j = 0; j < 32; j += 8) {
        int d = d0 + j;
        out[((size_t)(b * D_MODEL + d)) * SEQ + s] = tile[threadIdx.x][threadIdx.y + j];
    }
}

// ---------------------------------------------------------------------------
// LayerNorm: one block per row; emits fp16
// ---------------------------------------------------------------------------
__global__ void layernorm_kernel(const float* __restrict__ x,
                                 const float* __restrict__ scale,
                                 const float* __restrict__ offset,
                                 __half* __restrict__ out)
{
    int row = blockIdx.x;
    const float4* xr = reinterpret_cast<const float4*>(x + (size_t)row * D_MODEL);
    float4 vals[4];
    float s = 0.f, sq = 0.f;
#pragma unroll
    for (int p = 0; p < 4; p++) {
        float4 v = xr[threadIdx.x + p * 256];
        vals[p] = v;
        s  += v.x + v.y + v.z + v.w;
        sq += v.x*v.x + v.y*v.y + v.z*v.z + v.w*v.w;
    }
    __shared__ float shm[64];
#pragma unroll
    for (int o = 16; o > 0; o >>= 1) {
        s  += __shfl_xor_sync(0xffffffffu, s,  o);
        sq += __shfl_xor_sync(0xffffffffu, sq, o);
    }
    int w = threadIdx.x >> 5;
    if ((threadIdx.x & 31) == 0) { shm[w] = s; shm[w + 32] = sq; }
    __syncthreads();
    if (threadIdx.x < 32) {
        float a = (threadIdx.x < 8) ? shm[threadIdx.x]      : 0.f;
        float b = (threadIdx.x < 8) ? shm[32 + threadIdx.x] : 0.f;
#pragma unroll
        for (int o = 4; o > 0; o >>= 1) {
            a += __shfl_xor_sync(0xffffffffu, a, o);
            b += __shfl_xor_sync(0xffffffffu, b, o);
        }
        if (threadIdx.x == 0) { shm[0] = a; shm[1] = b; }
    }
    __syncthreads();
    float mean = shm[0] * (1.0f / D_MODEL);
    float var  = shm[1] * (1.0f / D_MODEL) - mean * mean;
    float inv  = rsqrtf(var + 1e-5f);
    const float4* sc4 = reinterpret_cast<const float4*>(scale);
    const float4* of4 = reinterpret_cast<const float4*>(offset);
    __half2* o2 = reinterpret_cast<__half2*>(out + (size_t)row * D_MODEL);
#pragma unroll
    for (int p = 0; p < 4; p++) {
        int i = threadIdx.x + p * 256;
        float4 v = vals[p], g = sc4[i], b = of4[i];
        o2[i * 2]     = __floats2half2_rn((v.x - mean) * inv * g.x + b.x,
                                          (v.y - mean) * inv * g.y + b.y);
        o2[i * 2 + 1] = __floats2half2_rn((v.z - mean) * inv * g.z + b.z,
                                          (v.w - mean) * inv * g.w + b.w);
    }
}

// ---------------------------------------------------------------------------
// RoPE on packed qkv (q at col 0, k at col 4096; row stride QKVW)
// ---------------------------------------------------------------------------
__global__ void rope_kernel(__half* __restrict__ qkv)
{
    const int HALF = ROTARY / 2;
    int idx = blockIdx.x * blockDim.x + threadIdx.x;
    int total = NROWS * N_HEADS * HALF;
    if (idx >= total) return;
    int i  = idx % HALF;
    int h  = (idx / HALF) % N_HEADS;
    int bt = idx / (HALF * N_HEADS);
    int t  = bt % SEQ;

    float inv_freq = powf(10000.0f, -(float)i / (float)HALF);
    float fr = (float)t * inv_freq;
    float sn, cs;
    sincosf(fr, &sn, &cs);

    size_t base = (size_t)bt * QKVW + (size_t)h * D_HEAD + 2 * i;
    __half2* qp = reinterpret_cast<__half2*>(qkv + base);
    __half2* kp = reinterpret_cast<__half2*>(qkv + base + D_MODEL);
    float2 qv = __half22float2(*qp);
    float2 kv = __half22float2(*kp);
    *qp = __floats2half2_rn(qv.x * cs - qv.y * sn, qv.y * cs + qv.x * sn);
    *kp = __floats2half2_rn(kv.x * cs - kv.y * sn, kv.y * cs + kv.x * sn);
}

// ---------------------------------------------------------------------------
// Causal softmax: fp32 scores -> fp16 probs.  Skips chunks entirely beyond
// the causal bound on BOTH read and write.
// ---------------------------------------------------------------------------
__global__ void softmax_kernel(const float* __restrict__ scores, __half* __restrict__ probs)
{
    size_t r = blockIdx.x;
    int t = blockIdx.x % SEQ;
    const float* row = scores + r * SEQ;
    __half* prow = probs + r * SEQ;
    const float sc = 1.0f / 16.0f;
    int bound = ((t >> 7) + 1) << 7;

    float v[8];
    float mx = -1e30f;
#pragma unroll
    for (int j = 0; j < 8; j++) {
        int col = threadIdx.x + j * 256;
        float xv = -1e30f;
        if (j * 256 <= t) {                       // chunk intersects causal region
            float raw = row[col];
            if (col <= t) xv = raw * sc;
        }
        v[j] = xv;
        mx = fmaxf(mx, xv);
    }
    __shared__ float shm[32];
#pragma unroll
    for (int o = 16; o > 0; o >>= 1) mx = fmaxf(mx, __shfl_xor_sync(0xffffffffu, mx, o));
    if ((threadIdx.x & 31) == 0) shm[threadIdx.x >> 5] = mx;
    __syncthreads();
    if (threadIdx.x < 32) {
        float m = (threadIdx.x < 8) ? shm[threadIdx.x] : -1e30f;
#pragma unroll
        for (int o = 4; o > 0; o >>= 1) m = fmaxf(m, __shfl_xor_sync(0xffffffffu, m, o));
        if (threadIdx.x == 0) shm[0] = m;
    }
    __syncthreads();
    mx = shm[0];
    __syncthreads();

    float s = 0.f;
#pragma unroll
    for (int j = 0; j < 8; j++) { float e = expf(v[j] - mx); v[j] = e; s += e; }
#pragma unroll
    for (int o = 16; o > 0; o >>= 1) s += __shfl_xor_sync(0xffffffffu, s, o);
    if ((threadIdx.x & 31) == 0) shm[threadIdx.x >> 5] = s;
    __syncthreads();
    if (threadIdx.x < 32) {
        float a = (threadIdx.x < 8) ? shm[threadIdx.x] : 0.f;
#pragma unroll
        for (int o = 4; o > 0; o >>= 1) a += __shfl_xor_sync(0xffffffffu, a, o);
        if (threadIdx.x == 0) shm[0] = a;
    }
    __syncthreads();
    float inv = 1.0f / shm[0];
#pragma unroll
    for (int j = 0; j < 8; j++) {
        if (j * 256 < bound)
            prow[threadIdx.x + j * 256] = __float2half_rn(v[j] * inv);
    }
}

// ---------------------------------------------------------------------------
// FP16 tensor-core GEMM: C[M,N] = A[M,K] @ Bt[N,K]^T (+epi)
//   128x128 CTA tile, __launch_bounds__(256,2) -> 2 CTAs/SM (16 warps).
//   m16n8k16 MMA via ldmatrix.b16; cp.async 3-stage, BK=64 halfs.
//   PERSIST: grid-stride over output tiles (gx tiles in n, nTiles total).
//   EPI: 0 none | 1 bias+gelu | 2 +Res | 3 bias+Res
//   OUT: 0 f32 | 2 fp16
//   CSKIP: causal tile skip (scores).  CKT: causal K truncation (ctx).
// ---------------------------------------------------------------------------
template<int EPI, int OUT, bool CSKIP, bool CKT, bool PERSIST>
__global__ void __launch_bounds__(256, 2)
gemm_h(const __half* __restrict__ A, const __half* __restrict__ Bt,
       void* __restrict__ Cv, const float* __restrict__ bias,
       const float* __restrict__ Res,
       int K, int lda, int ldb, int ldc,
       long sAb, long sAh, long sBb, long sBh, long sCb, long sCh, int Hb,
       int gx, int nTiles)
{
    extern __shared__ char smem_dyn[];
    uint32_t aBase = (uint32_t)__cvta_generic_to_shared(smem_dyn);
    uint32_t bBase = aBase + STAGES * STGB;

    int tid = threadIdx.x;
    int lane = tid & 31, warp = tid >> 5;
    int wm = warp & 3, wn = warp >> 2;
    int g  = lane >> 2, tg = lane & 3;
    int lc = tid & 7, lr = tid >> 3;

    int lane_row = (lane & 7) | (((lane >> 3) & 1) << 3);  // 0..15
    int lane_kb  = (lane >> 4) << 4;                        // 0 or 16 bytes
    uint32_t aoff0 = (uint32_t)((wm * 32 + lane_row) * ROWB + lane_kb);
    uint32_t boff0 = (uint32_t)((wn * 64 + lane_row) * ROWB + lane_kb);

    const __half* Ab = A; const __half* Bb = Bt;
    float* Cfb = reinterpret_cast<float*>(Cv);
    __half* Chb = reinterpret_cast<__half*>(Cv);
    if (!PERSIST) {
        int z = blockIdx.z;
        int b = z / Hb, hh = z % Hb;
        Ab  += (size_t)b * sAb + (size_t)hh * sAh;
        Bb  += (size_t)b * sBb + (size_t)hh * sBh;
        Cfb += (size_t)b * sCb + (size_t)hh * sCh;
        Chb += (size_t)b * sCb + (size_t)hh * sCh;
    }

    int tiles = PERSIST ? nTiles : 1;
    for (int tix = PERSIST ? blockIdx.x : 0; tix < tiles;
         tix += PERSIST ? gridDim.x : 1) {

        int m0, n0;
        if (PERSIST) { m0 = (tix / gx) * 128; n0 = (tix % gx) * 128; }
        else         { m0 = blockIdx.y * 128; n0 = blockIdx.x * 128; }

        bool active = true;
        if (CSKIP) { if (n0 > m0 + 127) active = false; }

        if (active) {
            if (PERSIST) __syncthreads();   // protect smem reuse across tiles

            float acc[2][8][4] = {};

            int KT = K >> 6;
            if (CKT) { int lim = (m0 + 128) >> 6; if (lim < KT) KT = lim; }

            auto loadTile = [&](int kt, int s) {
                const __half* ap = Ab + (size_t)m0 * lda + (size_t)kt * 64;
#pragma unroll
                for (int p = 0; p < 4; p++) {
                    int row = lr + p * 32;
                    cp16(aBase + (uint32_t)(s * STGB + row * ROWB + lc * 16),
                         ap + (size_t)row * lda + lc * 8);
                }
                const __half* bp = Bb + (size_t)n0 * ldb + (size_t)kt * 64;
#pragma unroll
                for (int p = 0; p < 4; p++) {
                    int row = lr + p * 32;
                    cp16(bBase + (uint32_t)(s * STGB + row * ROWB + lc * 16),
                         bp + (size_t)row * ldb + lc * 8);
                }
            };

            loadTile(0, 0); cp_commit();
            if (KT > 1) loadTile(1, 1);
            cp_commit();

            for (int kt = 0; kt < KT; kt++) {
                cp_wait1();
                __syncthreads();
                int s = kt % STAGES;
                uint32_t aS = aBase + (uint32_t)(s * STGB) + aoff0;
                uint32_t bS = bBase + (uint32_t)(s * STGB) + boff0;

#pragma unroll
                for (int kk = 0; kk < 4; kk++) {
                    uint32_t af[2][4], bf[8][2];
                    uint32_t kkb = kk * 32;
#pragma unroll
                    for (int mt = 0; mt < 2; mt++)
                        ldsm4(af[mt][0], af[mt][1], af[mt][2], af[mt][3],
                              aS + (uint32_t)(mt * 16 * ROWB) + kkb);
#pragma unroll
                    for (int p = 0; p < 4; p++)
                        ldsm4(bf[2*p][0], bf[2*p+1][0], bf[2*p][1], bf[2*p+1][1],
                              bS + (uint32_t)(p * 16 * ROWB) + kkb);
#pragma unroll
                    for (int mt = 0; mt < 2; mt++)
#pragma unroll
                        for (int nt = 0; nt < 8; nt++) {
                            asm volatile(
                                "mma.sync.aligned.m16n8k16.row.col.f32.f16.f16.f32 "
                                "{%0,%1,%2,%3}, {%4,%5,%6,%7}, {%8,%9}, {%0,%1,%2,%3};\n"
                                : "+f"(acc[mt][nt][0]), "+f"(acc[mt][nt][1]),
                                  "+f"(acc[mt][nt][2]), "+f"(acc[mt][nt][3])
                                : "r"(af[mt][0]), "r"(af[mt][1]), "r"(af[mt][2]), "r"(af[mt][3]),
                                  "r"(bf[nt][0]), "r"(bf[nt][1]));
                        }
                }

                if (kt + 2 < KT) loadTile(kt + 2, (kt + 2) % STAGES);
                cp_commit();
            }

            // Epilogue
#pragma unroll
            for (int mt = 0; mt < 2; mt++) {
#pragma unroll
                for (int nt = 0; nt < 8; nt++) {
                    int row0 = m0 + wm * 32 + mt * 16 + g;
                    int col  = n0 + wn * 64 + nt * 8 + 2 * tg;
#pragma unroll
                    for (int rr = 0; rr < 2; rr++) {
                        int row = row0 + rr * 8;
                        float v0 = acc[mt][nt][rr * 2 + 0];
                        float v1 = acc[mt][nt][rr * 2 + 1];
                        if (EPI == 1) {
                            v0 = gelu_f(v0 + bias[col]);
                            v1 = gelu_f(v1 + bias[col + 1]);
                        } else if (EPI == 2) {
                            float2 rv = *reinterpret_cast<const float2*>(
                                &Res[(size_t)row * ldc + col]);
                            v0 += rv.x; v1 += rv.y;
                        } else if (EPI == 3) {
                            float2 rv = *reinterpret_cast<const float2*>(
                                &Res[(size_t)row * ldc + col]);
                            v0 += bias[col] + rv.x; v1 += bias[col + 1] + rv.y;
                        }
                        if (OUT == 2) {
                            *reinterpret_cast<__half2*>(&Chb[(size_t)row * ldc + col]) =
                                __floats2half2_rn(v0, v1);
                        } else {
                            float2 ov; ov.x = v0; ov.y = v1;
                            *reinterpret_cast<float2*>(&Cfb[(size_t)row * ldc + col]) = ov;
                        }
                    }
                }
            }
        }
    }
}

// ---------------------------------------------------------------------------
// Launch
// ---------------------------------------------------------------------------
extern "C" void kernel_launch(void* const* d_in, const int* in_sizes, int n_in,
                              void* d_out, int out_size)
{
    (void)in_sizes; (void)n_in; (void)out_size;
    const float* x     = (const float*)d_in[0];
    const float* lns   = (const float*)d_in[1];
    const float* lno   = (const float*)d_in[2];
    const float* wq    = (const float*)d_in[3];
    const float* wk    = (const float*)d_in[4];
    const float* wv    = (const float*)d_in[5];
    const float* wo    = (const float*)d_in[6];
    const float* w_in  = (const float*)d_in[7];
    const float* b_in  = (const float*)d_in[8];
    const float* w_out = (const float*)d_in[9];
    const float* b_out = (const float*)d_in[10];
    float* out = (float*)d_out;

    __half *xn, *xn2, *qkv, *vt, *ctx, *hbuf, *p, *wh;
    float *x2, *sc;
    cudaGetSymbolAddress((void**)&xn,   g_xn);
    cudaGetSymbolAddress((void**)&xn2,  g_xn2);
    cudaGetSymbolAddress((void**)&qkv,  g_qkv);
    cudaGetSymbolAddress((void**)&vt,   g_vt);
    cudaGetSymbolAddress((void**)&ctx,  g_ctx);
    cudaGetSymbolAddress((void**)&hbuf, g_h);
    cudaGetSymbolAddress((void**)&p,    g_p);
    cudaGetSymbolAddress((void**)&wh,   g_wh);
    cudaGetSymbolAddress((void**)&x2,   g_x2);
    cudaGetSymbolAddress((void**)&sc,   g_sc);

    const size_t WSZ = (size_t)D_MODEL * D_MODEL;
    __half* wqT  = wh;                              // rows 0-4095      of packed [12288][4096]
    __half* wkT  = wh + WSZ;                        // rows 4096-8191
    __half* wvT  = wh + 2 * WSZ;                    // rows 8192-12287
    __half* woT  = wh + 3 * WSZ;
    __half* winT = wh + 4 * WSZ;                    // [D_FF, D_MODEL]
    __half* wouT = winT + (size_t)D_MODEL * D_FF;   // [D_MODEL, D_FF]

    cudaFuncSetAttribute(gemm_h<0,2,false,false,true >, cudaFuncAttributeMaxDynamicSharedMemorySize, SMH);
    cudaFuncSetAttribute(gemm_h<2,0,false,false,true >, cudaFuncAttributeMaxDynamicSharedMemorySize, SMH);
    cudaFuncSetAttribute(gemm_h<1,2,false,false,true >, cudaFuncAttributeMaxDynamicSharedMemorySize, SMH);
    cudaFuncSetAttribute(gemm_h<3,0,false,false,true >, cudaFuncAttributeMaxDynamicSharedMemorySize, SMH);
    cudaFuncSetAttribute(gemm_h<0,0,true ,false,false>, cudaFuncAttributeMaxDynamicSharedMemorySize, SMH);
    cudaFuncSetAttribute(gemm_h<0,2,false,true ,false>, cudaFuncAttributeMaxDynamicSharedMemorySize, SMH);

    dim3 tb(32, 8);

    // 1-3. Transpose + fp16-convert all weights into [N,K]
    transpose4_kernel<<<dim3(128, 128, 4), tb>>>(wq, wk, wv, wo, wqT, wkT, wvT, woT);
    transpose_rc_kernel<<<dim3(D_FF / 32, D_MODEL / 32), tb>>>(w_in,  winT, D_MODEL, D_FF);
    transpose_rc_kernel<<<dim3(D_MODEL / 32, D_FF / 32), tb>>>(w_out, wouT, D_FF, D_MODEL);

    // 4. LayerNorm (emits fp16)
    layernorm_kernel<<<NROWS, 256>>>(x, lns, lno, xn);

    // 5. Merged QKV projection (persistent; packed fp16 out, ldc = 12288)
    gemm_h<0,2,false,false,true ><<<PERSIST_CTAS, 256, SMH>>>(xn, wh, qkv, nullptr, nullptr,
        D_MODEL, D_MODEL, D_MODEL, QKVW, 0, 0, 0, 0, 0, 0, 1,
        QKVW / 128, (QKVW / 128) * (NROWS / 128));

    // 6. RoPE on packed qkv
    {
        int total = NROWS * N_HEADS * (ROTARY / 2);
        rope_kernel<<<(total + 255) / 256, 256>>>(qkv);
    }

    // 7. Per-head V transpose -> Vt (k-contiguous)
    transpose_v_kernel<<<dim3(D_MODEL / 32, NROWS / 32), tb>>>(qkv + 2 * D_MODEL, QKVW, vt);

    // 8. scores = q @ k^T (causal tile-skip, batched b,h; C fp32)
    dim3 gS(SEQ / 128, SEQ / 128, BATCH * N_HEADS);
    gemm_h<0,0,true ,false,false><<<gS, 256, SMH>>>(qkv, qkv + D_MODEL, sc, nullptr, nullptr,
        D_HEAD, QKVW, QKVW, SEQ,
        (long)SEQ * QKVW, (long)D_HEAD,
        (long)SEQ * QKVW, (long)D_HEAD,
        (long)N_HEADS * SEQ * SEQ, (long)SEQ * SEQ, N_HEADS, 0, 0);

    // 9. causal softmax (fp32 scores -> fp16 probs; read+write bounded)
    softmax_kernel<<<BATCH * N_HEADS * SEQ, 256>>>(sc, p);

    // 10. ctx = probs @ Vt^T (fp16, causal K-trunc; C fp16)
    dim3 gC(D_HEAD / 128, SEQ / 128, BATCH * N_HEADS);
    gemm_h<0,2,false,true ,false><<<gC, 256, SMH>>>(p, vt, ctx, nullptr, nullptr,
        SEQ, SEQ, SEQ, D_MODEL,
        (long)N_HEADS * SEQ * SEQ, (long)SEQ * SEQ,
        (long)N_HEADS * D_HEAD * SEQ, (long)D_HEAD * SEQ,
        (long)SEQ * D_MODEL, (long)D_HEAD, N_HEADS, 0, 0);

    // 11. x2 = x + ctx @ wo (persistent; C fp32)
    gemm_h<2,0,false,false,true ><<<PERSIST_CTAS, 256, SMH>>>(ctx, woT, x2, nullptr, x,
        D_MODEL, D_MODEL, D_MODEL, D_MODEL, 0, 0, 0, 0, 0, 0, 1,
        D_MODEL / 128, (D_MODEL / 128) * (NROWS / 128));

    // 12. LayerNorm 2 (emits fp16)
    layernorm_kernel<<<NROWS, 256>>>(x2, lns, lno, xn2);

    // 13. h = gelu(xn2 @ w_in + b_in) (persistent; C fp16)
    gemm_h<1,2,false,false,true ><<<PERSIST_CTAS, 256, SMH>>>(xn2, winT, hbuf, b_in, nullptr,
        D_MODEL, D_MODEL, D_MODEL, D_FF, 0, 0, 0, 0, 0, 0, 1,
        D_FF / 128, (D_FF / 128) * (NROWS / 128));

    // 14. out = x2 + h @ w_out + b_out (persistent; C fp32)
    gemm_h<3,0,false,false,true ><<<PERSIST_CTAS, 256, SMH>>>(hbuf, wouT, out, b_out, x2,
        D_FF, D_FF, D_FF, D_MODEL, 0, 0, 0, 0, 0, 0, 1,
        D_MODEL / 128, (D_MODEL / 128) * (NROWS / 128));
}

// round 13
// speedup vs baseline: 1.0580x; 1.0580x over previous
#include <cuda_runtime.h>
#include <cuda_fp16.h>
#include <cstdint>
#include <math.h>

#define D_MODEL 4096
#define N_HEADS 16
#define D_HEAD  256
#define ROTARY  64
#define D_FF    16384
#define BATCH   2
#define SEQ     2048
#define NROWS   (BATCH*SEQ)   /* 4096 */
#define QKVW    12288         /* packed qkv row width */

#define STAGES 3
/* fp16 GEMM: BK=64 halfs, row stride 72 halfs = 144B (LDSM conflict-free) */
#define ROWB 144
#define STGB (128 * ROWB)          /* per-stage bytes per operand: 18,432 */
#define SMH  (STAGES * 2 * STGB)   /* 110,592 */

// ---------------------------------------------------------------------------
// Scratch (static device globals; no allocation allowed)
// ---------------------------------------------------------------------------
__device__ __align__(16) __half g_xn [(size_t)NROWS * D_MODEL];
__device__ __align__(16) __half g_xn2[(size_t)NROWS * D_MODEL];
__device__ __align__(16) __half g_qkv[(size_t)NROWS * QKVW];      // packed q|k|v
__device__ __align__(16) __half g_vt [(size_t)NROWS * D_MODEL];   // per-head V^T
__device__ __align__(16) __half g_ctx[(size_t)NROWS * D_MODEL];
__device__ __align__(16) __half g_h  [(size_t)NROWS * D_FF];
__device__ __align__(16) __half g_p  [(size_t)BATCH * N_HEADS * SEQ * SEQ]; // 256 MB probs
__device__ __align__(16) __half g_wh [(size_t)201326592];                   // 384 MB W^T fp16
__device__ __align__(16) float  g_x2 [(size_t)NROWS * D_MODEL];
__device__ __align__(16) float  g_sc [(size_t)BATCH * N_HEADS * SEQ * SEQ]; // 512 MB scores

// ---------------------------------------------------------------------------
// Helpers
// ---------------------------------------------------------------------------
__device__ __forceinline__ float gelu_f(float x) {
    return 0.5f * x * (1.0f + tanhf(0.7978845608028654f * (x + 0.044715f * x * x * x)));
}
__device__ __forceinline__ void cp16(uint32_t dst, const void* src) {
    asm volatile("cp.async.cg.shared.global [%0], [%1], 16;\n" :: "r"(dst), "l"(src));
}
__device__ __forceinline__ void cp_commit() {
    asm volatile("cp.async.commit_group;\n" ::: "memory");
}
__device__ __forceinline__ void cp_wait1() {
    asm volatile("cp.async.wait_group 1;\n" ::: "memory");
}
__device__ __forceinline__ void ldsm4(uint32_t& r0, uint32_t& r1, uint32_t& r2, uint32_t& r3,
                                      uint32_t addr) {
    asm volatile("ldmatrix.sync.aligned.m8n8.x4.shared.b16 {%0,%1,%2,%3}, [%4];"
                 : "=r"(r0), "=r"(r1), "=r"(r2), "=r"(r3) : "r"(addr));
}

// ---------------------------------------------------------------------------
// Weight transpose + fp16 convert: out[c][r] = half(in[r][c])
// ---------------------------------------------------------------------------
__global__ void transpose4_kernel(const float* __restrict__ w0, const float* __restrict__ w1,
                                  const float* __restrict__ w2, const float* __restrict__ w3,
                                  __half* __restrict__ o0, __half* __restrict__ o1,
                                  __half* __restrict__ o2, __half* __restrict__ o3)
{
    __shared__ float tile[32][33];
    const float* in; __half* out;
    switch (blockIdx.z) {
        case 0: in = w0; out = o0; break;
        case 1: in = w1; out = o1; break;
        case 2: in = w2; out = o2; break;
        default: in = w3; out = o3; break;
    }
    int x = blockIdx.x * 32 + threadIdx.x;
    int y = blockIdx.y * 32 + threadIdx.y;
#pragma unroll
    for (int j = 0; j < 32; j += 8)
        tile[threadIdx.y + j][threadIdx.x] = in[(size_t)(y + j) * 4096 + x];
    __syncthreads();
    x = blockIdx.y * 32 + threadIdx.x;
    y = blockIdx.x * 32 + threadIdx.y;
#pragma unroll
    for (int j = 0; j < 32; j += 8)
        out[(size_t)(y + j) * 4096 + x] = __float2half_rn(tile[threadIdx.x][threadIdx.y + j]);
}

__global__ void transpose_rc_kernel(const float* __restrict__ in, __half* __restrict__ out,
                                    int R, int C)
{
    __shared__ float tile[32][33];
    int x = blockIdx.x * 32 + threadIdx.x;
    int y = blockIdx.y * 32 + threadIdx.y;
#pragma unroll
    for (int j = 0; j < 32; j += 8)
        tile[threadIdx.y + j][threadIdx.x] = in[(size_t)(y + j) * C + x];
    __syncthreads();
    x = blockIdx.y * 32 + threadIdx.x;
    y = blockIdx.x * 32 + threadIdx.y;
#pragma unroll
    for (int j = 0; j < 32; j += 8)
        out[(size_t)(y + j) * R + x] = __float2half_rn(tile[threadIdx.x][threadIdx.y + j]);
}

// V (strided in qkv) -> Vt [(b*4096 + h*256 + d)][s] fp16 (k-contiguous per head)
__global__ void transpose_v_kernel(const __half* __restrict__ in, int ldin,
                                   __half* __restrict__ out)
{
    __shared__ __half tile[32][33];
    int x = blockIdx.x * 32 + threadIdx.x;    // dmodel col
    int y = blockIdx.y * 32 + threadIdx.y;    // bt row
#pragma unroll
    for (int j = 0; j < 32; j += 8)
        tile[threadIdx.y + j][threadIdx.x] = in[(size_t)(y + j) * ldin + x];
    __syncthreads();
    int d0 = blockIdx.x * 32 + threadIdx.y;   // dmodel index base
    int yo = blockIdx.y * 32 + threadIdx.x;   // bt index
    int b = yo >> 11, s = yo & (SEQ - 1);
#pragma unroll
    for (int j = 0; j < 32; j += 8) {
        int d = d0 + j;
        out[((size_t)(b * D_MODEL + d)) * SEQ + s] = tile[threadIdx.x][threadIdx.y + j];
    }
}

// ---------------------------------------------------------------------------
// LayerNorm: one block per row; emits fp16
// ---------------------------------------------------------------------------
__global__ void layernorm_kernel(const float* __restrict__ x,
                                 const float* __restrict__ scale,
                                 const float* __restrict__ offset,
                                 __half* __restrict__ out)
{
    int row = blockIdx.x;
    const float4* xr = reinterpret_cast<const float4*>(x + (size_t)row * D_MODEL);
    float4 vals[4];
    float s = 0.f, sq = 0.f;
#pragma unroll
    for (int p = 0; p < 4; p++) {
        float4 v = xr[threadIdx.x + p * 256];
        vals[p] = v;
        s  += v.x + v.y + v.z + v.w;
        sq += v.x*v.x + v.y*v.y + v.z*v.z + v.w*v.w;
    }
    __shared__ float shm[64];
#pragma unroll
    for (int o = 16; o > 0; o >>= 1) {
        s  += __shfl_xor_sync(0xffffffffu, s,  o);
        sq += __shfl_xor_sync(0xffffffffu, sq, o);
    }
    int w = threadIdx.x >> 5;
    if ((threadIdx.x & 31) == 0) { shm[w] = s; shm[w + 32] = sq; }
    __syncthreads();
    if (threadIdx.x < 32) {
        float a = (threadIdx.x < 8) ? shm[threadIdx.x]      : 0.f;
        float b = (threadIdx.x < 8) ? shm[32 + threadIdx.x] : 0.f;
#pragma unroll
        for (int o = 4; o > 0; o >>= 1) {
            a += __shfl_xor_sync(0xffffffffu, a, o);
            b += __shfl_xor_sync(0xffffffffu, b, o);
        }
        if (threadIdx.x == 0) { shm[0] = a; shm[1] = b; }
    }
    __syncthreads();
    float mean = shm[0] * (1.0f / D_MODEL);
    float var  = shm[1] * (1.0f / D_MODEL) - mean * mean;
    float inv  = rsqrtf(var + 1e-5f);
    const float4* sc4 = reinterpret_cast<const float4*>(scale);
    const float4* of4 = reinterpret_cast<const float4*>(offset);
    __half2* o2 = reinterpret_cast<__half2*>(out + (size_t)row * D_MODEL);
#pragma unroll
    for (int p = 0; p < 4; p++) {
        int i = threadIdx.x + p * 256;
        float4 v = vals[p], g = sc4[i], b = of4[i];
        o2[i * 2]     = __floats2half2_rn((v.x - mean) * inv * g.x + b.x,
                                          (v.y - mean) * inv * g.y + b.y);
        o2[i * 2 + 1] = __floats2half2_rn((v.z - mean) * inv * g.z + b.z,
                                          (v.w - mean) * inv * g.w + b.w);
    }
}

// ---------------------------------------------------------------------------
// RoPE on packed qkv (q at col 0, k at col 4096; row stride QKVW)
// ---------------------------------------------------------------------------
__global__ void rope_kernel(__half* __restrict__ qkv)
{
    const int HALF = ROTARY / 2;
    int idx = blockIdx.x * blockDim.x + threadIdx.x;
    int total = NROWS * N_HEADS * HALF;
    if (idx >= total) return;
    int i  = idx % HALF;
    int h  = (idx / HALF) % N_HEADS;
    int bt = idx / (HALF * N_HEADS);
    int t  = bt % SEQ;

    float inv_freq = powf(10000.0f, -(float)i / (float)HALF);
    float fr = (float)t * inv_freq;
    float sn, cs;
    sincosf(fr, &sn, &cs);

    size_t base = (size_t)bt * QKVW + (size_t)h * D_HEAD + 2 * i;
    __half2* qp = reinterpret_cast<__half2*>(qkv + base);
    __half2* kp = reinterpret_cast<__half2*>(qkv + base + D_MODEL);
    float2 qv = __half22float2(*qp);
    float2 kv = __half22float2(*kp);
    *qp = __floats2half2_rn(qv.x * cs - qv.y * sn, qv.y * cs + qv.x * sn);
    *kp = __floats2half2_rn(kv.x * cs - kv.y * sn, kv.y * cs + kv.x * sn);
}

// ---------------------------------------------------------------------------
// Causal softmax: fp32 scores -> fp16 probs.  Skips chunks entirely beyond
// the causal bound on BOTH read and write.
// ---------------------------------------------------------------------------
__global__ void softmax_kernel(const float* __restrict__ scores, __half* __restrict__ probs)
{
    size_t r = blockIdx.x;
    int t = blockIdx.x % SEQ;
    const float* row = scores + r * SEQ;
    __half* prow = probs + r * SEQ;
    const float sc = 1.0f / 16.0f;
    int bound = ((t >> 7) + 1) << 7;

    float v[8];
    float mx = -1e30f;
#pragma unroll
    for (int j = 0; j < 8; j++) {
        int col = threadIdx.x + j * 256;
        float xv = -1e30f;
        if (j * 256 <= t) {                       // chunk intersects causal region
            float raw = row[col];
            if (col <= t) xv = raw * sc;
        }
        v[j] = xv;
        mx = fmaxf(mx, xv);
    }
    __shared__ float shm[32];
#pragma unroll
    for (int o = 16; o > 0; o >>= 1) mx = fmaxf(mx, __shfl_xor_sync(0xffffffffu, mx, o));
    if ((threadIdx.x & 31) == 0) shm[threadIdx.x >> 5] = mx;
    __syncthreads();
    if (threadIdx.x < 32) {
        float m = (threadIdx.x < 8) ? shm[threadIdx.x] : -1e30f;
#pragma unroll
        for (int o = 4; o > 0; o >>= 1) m = fmaxf(m, __shfl_xor_sync(0xffffffffu, m, o));
        if (threadIdx.x == 0) shm[0] = m;
    }
    __syncthreads();
    mx = shm[0];
    __syncthreads();

    float s = 0.f;
#pragma unroll
    for (int j = 0; j < 8; j++) { float e = expf(v[j] - mx); v[j] = e; s += e; }
#pragma unroll
    for (int o = 16; o > 0; o >>= 1) s += __shfl_xor_sync(0xffffffffu, s, o);
    if ((threadIdx.x & 31) == 0) shm[threadIdx.x >> 5] = s;
    __syncthreads();
    if (threadIdx.x < 32) {
        float a = (threadIdx.x < 8) ? shm[threadIdx.x] : 0.f;
#pragma unroll
        for (int o = 4; o > 0; o >>= 1) a += __shfl_xor_sync(0xffffffffu, a, o);
        if (threadIdx.x == 0) shm[0] = a;
    }
    __syncthreads();
    float inv = 1.0f / shm[0];
#pragma unroll
    for (int j = 0; j < 8; j++) {
        if (j * 256 < bound)
            prow[threadIdx.x + j * 256] = __float2half_rn(v[j] * inv);
    }
}

// ---------------------------------------------------------------------------
// FP16 tensor-core GEMM: C[M,N] = A[M,K] @ Bt[N,K]^T (+epi)
//   128x128 CTA tile, __launch_bounds__(256,2) -> 2 CTAs/SM (16 warps).
//   m16n8k16 MMA via ldmatrix.b16; cp.async 3-stage, BK=64 halfs.
//   Next-next tile loads are issued BEFORE the MMA block (overlap fetch).
//   EPI: 0 none | 1 bias+gelu | 2 +Res | 3 bias+Res
//   OUT: 0 f32 | 2 fp16
//   CSKIP: causal tile skip (scores).  CKT: causal K truncation (ctx).
// ---------------------------------------------------------------------------
template<int EPI, int OUT, bool CSKIP, bool CKT>
__global__ void __launch_bounds__(256, 2)
gemm_h(const __half* __restrict__ A, const __half* __restrict__ Bt,
       void* __restrict__ Cv, const float* __restrict__ bias,
       const float* __restrict__ Res,
       int K, int lda, int ldb, int ldc,
       long sAb, long sAh, long sBb, long sBh, long sCb, long sCh, int Hb)
{
    int m0 = blockIdx.y * 128;
    int n0 = blockIdx.x * 128;
    if (CSKIP) { if (n0 > m0 + 127) return; }

    int z = blockIdx.z;
    int b = z / Hb, hh = z % Hb;
    A  += (size_t)b * sAb + (size_t)hh * sAh;
    Bt += (size_t)b * sBb + (size_t)hh * sBh;
    float*  Cf = reinterpret_cast<float*>(Cv)  + (size_t)b * sCb + (size_t)hh * sCh;
    __half* Ch = reinterpret_cast<__half*>(Cv) + (size_t)b * sCb + (size_t)hh * sCh;

    extern __shared__ char smem_dyn[];
    uint32_t aBase = (uint32_t)__cvta_generic_to_shared(smem_dyn);
    uint32_t bBase = aBase + STAGES * STGB;

    int tid = threadIdx.x;
    int lane = tid & 31, warp = tid >> 5;
    int wm = warp & 3, wn = warp >> 2;
    int g  = lane >> 2, tg = lane & 3;
    int lc = tid & 7, lr = tid >> 3;

    float acc[2][8][4] = {};

    int KT = K >> 6;
    if (CKT) { int lim = (m0 + 128) >> 6; if (lim < KT) KT = lim; }

    auto loadTile = [&](int kt, int s) {
        const __half* ap = A + (size_t)m0 * lda + (size_t)kt * 64;
#pragma unroll
        for (int p = 0; p < 4; p++) {
            int row = lr + p * 32;
            cp16(aBase + (uint32_t)(s * STGB + row * ROWB + lc * 16),
                 ap + (size_t)row * lda + lc * 8);
        }
        const __half* bp = Bt + (size_t)n0 * ldb + (size_t)kt * 64;
#pragma unroll
        for (int p = 0; p < 4; p++) {
            int row = lr + p * 32;
            cp16(bBase + (uint32_t)(s * STGB + row * ROWB + lc * 16),
                 bp + (size_t)row * ldb + lc * 8);
        }
    };

    loadTile(0, 0); cp_commit();
    if (KT > 1) loadTile(1, 1);
    cp_commit();

    int lane_row = (lane & 7) | (((lane >> 3) & 1) << 3);  // 0..15
    int lane_kb  = (lane >> 4) << 4;                        // 0 or 16 bytes
    uint32_t aoff0 = (uint32_t)((wm * 32 + lane_row) * ROWB + lane_kb);
    uint32_t boff0 = (uint32_t)((wn * 64 + lane_row) * ROWB + lane_kb);

    for (int kt = 0; kt < KT; kt++) {
        cp_wait1();
        __syncthreads();
        // Issue next-next stage loads first so DRAM fetch overlaps the MMAs.
        // Stage (kt+2)%3 was last read at iter kt-1; the barrier above fences it.
        if (kt + 2 < KT) loadTile(kt + 2, (kt + 2) % STAGES);
        cp_commit();

        int s = kt % STAGES;
        uint32_t aS = aBase + (uint32_t)(s * STGB) + aoff0;
        uint32_t bS = bBase + (uint32_t)(s * STGB) + boff0;

#pragma unroll
        for (int kk = 0; kk < 4; kk++) {
            uint32_t af[2][4], bf[8][2];
            uint32_t kkb = kk * 32;
#pragma unroll
            for (int mt = 0; mt < 2; mt++)
                ldsm4(af[mt][0], af[mt][1], af[mt][2], af[mt][3],
                      aS + (uint32_t)(mt * 16 * ROWB) + kkb);
#pragma unroll
            for (int p = 0; p < 4; p++)
                ldsm4(bf[2*p][0], bf[2*p+1][0], bf[2*p][1], bf[2*p+1][1],
                      bS + (uint32_t)(p * 16 * ROWB) + kkb);
#pragma unroll
            for (int mt = 0; mt < 2; mt++)
#pragma unroll
                for (int nt = 0; nt < 8; nt++) {
                    asm volatile(
                        "mma.sync.aligned.m16n8k16.row.col.f32.f16.f16.f32 "
                        "{%0,%1,%2,%3}, {%4,%5,%6,%7}, {%8,%9}, {%0,%1,%2,%3};\n"
                        : "+f"(acc[mt][nt][0]), "+f"(acc[mt][nt][1]),
                          "+f"(acc[mt][nt][2]), "+f"(acc[mt][nt][3])
                        : "r"(af[mt][0]), "r"(af[mt][1]), "r"(af[mt][2]), "r"(af[mt][3]),
                          "r"(bf[nt][0]), "r"(bf[nt][1]));
                }
        }
    }

    // Epilogue
#pragma unroll
    for (int mt = 0; mt < 2; mt++) {
#pragma unroll
        for (int nt = 0; nt < 8; nt++) {
            int row0 = m0 + wm * 32 + mt * 16 + g;
            int col  = n0 + wn * 64 + nt * 8 + 2 * tg;
#pragma unroll
            for (int rr = 0; rr < 2; rr++) {
                int row = row0 + rr * 8;
                float v0 = acc[mt][nt][rr * 2 + 0];
                float v1 = acc[mt][nt][rr * 2 + 1];
                if (EPI == 1) {
                    v0 = gelu_f(v0 + bias[col]);
                    v1 = gelu_f(v1 + bias[col + 1]);
                } else if (EPI == 2) {
                    float2 rv = *reinterpret_cast<const float2*>(&Res[(size_t)row * ldc + col]);
                    v0 += rv.x; v1 += rv.y;
                } else if (EPI == 3) {
                    float2 rv = *reinterpret_cast<const float2*>(&Res[(size_t)row * ldc + col]);
                    v0 += bias[col] + rv.x; v1 += bias[col + 1] + rv.y;
                }
                if (OUT == 2) {
                    *reinterpret_cast<__half2*>(&Ch[(size_t)row * ldc + col]) =
                        __floats2half2_rn(v0, v1);
                } else {
                    float2 ov; ov.x = v0; ov.y = v1;
                    *reinterpret_cast<float2*>(&Cf[(size_t)row * ldc + col]) = ov;
                }
            }
        }
    }
}

// ---------------------------------------------------------------------------
// Launch
// ---------------------------------------------------------------------------
extern "C" void kernel_launch(void* const* d_in, const int* in_sizes, int n_in,
                              void* d_out, int out_size)
{
    (void)in_sizes; (void)n_in; (void)out_size;
    const float* x     = (const float*)d_in[0];
    const float* lns   = (const float*)d_in[1];
    const float* lno   = (const float*)d_in[2];
    const float* wq    = (const float*)d_in[3];
    const float* wk    = (const float*)d_in[4];
    const float* wv    = (const float*)d_in[5];
    const float* wo    = (const float*)d_in[6];
    const float* w_in  = (const float*)d_in[7];
    const float* b_in  = (const float*)d_in[8];
    const float* w_out = (const float*)d_in[9];
    const float* b_out = (const float*)d_in[10];
    float* out = (float*)d_out;

    __half *xn, *xn2, *qkv, *vt, *ctx, *hbuf, *p, *wh;
    float *x2, *sc;
    cudaGetSymbolAddress((void**)&xn,   g_xn);
    cudaGetSymbolAddress((void**)&xn2,  g_xn2);
    cudaGetSymbolAddress((void**)&qkv,  g_qkv);
    cudaGetSymbolAddress((void**)&vt,   g_vt);
    cudaGetSymbolAddress((void**)&ctx,  g_ctx);
    cudaGetSymbolAddress((void**)&hbuf, g_h);
    cudaGetSymbolAddress((void**)&p,    g_p);
    cudaGetSymbolAddress((void**)&wh,   g_wh);
    cudaGetSymbolAddress((void**)&x2,   g_x2);
    cudaGetSymbolAddress((void**)&sc,   g_sc);

    const size_t WSZ = (size_t)D_MODEL * D_MODEL;
    __half* wqT  = wh;                              // rows 0-4095 of packed [12288][4096]
    __half* wkT  = wh + WSZ;                        // rows 4096-8191
    __half* wvT  = wh + 2 * WSZ;                    // rows 8192-12287
    __half* woT  = wh + 3 * WSZ;
    __half* winT = wh + 4 * WSZ;                    // [D_FF, D_MODEL]
    __half* wouT = winT + (size_t)D_MODEL * D_FF;   // [D_MODEL, D_FF]

    cudaFuncSetAttribute(gemm_h<0,2,false,false>, cudaFuncAttributeMaxDynamicSharedMemorySize, SMH);
    cudaFuncSetAttribute(gemm_h<0,0,true ,false>, cudaFuncAttributeMaxDynamicSharedMemorySize, SMH);
    cudaFuncSetAttribute(gemm_h<0,2,false,true >, cudaFuncAttributeMaxDynamicSharedMemorySize, SMH);
    cudaFuncSetAttribute(gemm_h<2,0,false,false>, cudaFuncAttributeMaxDynamicSharedMemorySize, SMH);
    cudaFuncSetAttribute(gemm_h<1,2,false,false>, cudaFuncAttributeMaxDynamicSharedMemorySize, SMH);
    cudaFuncSetAttribute(gemm_h<3,0,false,false>, cudaFuncAttributeMaxDynamicSharedMemorySize, SMH);

    dim3 tb(32, 8);

    // 1-3. Transpose + fp16-convert all weights into [N,K]
    transpose4_kernel<<<dim3(128, 128, 4), tb>>>(wq, wk, wv, wo, wqT, wkT, wvT, woT);
    transpose_rc_kernel<<<dim3(D_FF / 32, D_MODEL / 32), tb>>>(w_in,  winT, D_MODEL, D_FF);
    transpose_rc_kernel<<<dim3(D_MODEL / 32, D_FF / 32), tb>>>(w_out, wouT, D_FF, D_MODEL);

    // 4. LayerNorm (emits fp16)
    layernorm_kernel<<<NROWS, 256>>>(x, lns, lno, xn);

    // 5. Merged QKV projection: ONE ordinary launch, packed fp16 out (ldc=12288)
    dim3 gQ(QKVW / 128, NROWS / 128, 1);
    gemm_h<0,2,false,false><<<gQ, 256, SMH>>>(xn, wh, qkv, nullptr, nullptr,
        D_MODEL, D_MODEL, D_MODEL, QKVW, 0, 0, 0, 0, 0, 0, 1);

    // 6. RoPE on packed qkv
    {
        int total = NROWS * N_HEADS * (ROTARY / 2);
        rope_kernel<<<(total + 255) / 256, 256>>>(qkv);
    }

    // 7. Per-head V transpose -> Vt (k-contiguous)
    transpose_v_kernel<<<dim3(D_MODEL / 32, NROWS / 32), tb>>>(qkv + 2 * D_MODEL, QKVW, vt);

    // 8. scores = q @ k^T (causal tile-skip, batched b,h; C fp32)
    dim3 gS(SEQ / 128, SEQ / 128, BATCH * N_HEADS);
    gemm_h<0,0,true ,false><<<gS, 256, SMH>>>(qkv, qkv + D_MODEL, sc, nullptr, nullptr,
        D_HEAD, QKVW, QKVW, SEQ,
        (long)SEQ * QKVW, (long)D_HEAD,
        (long)SEQ * QKVW, (long)D_HEAD,
        (long)N_HEADS * SEQ * SEQ, (long)SEQ * SEQ, N_HEADS);

    // 9. causal softmax (fp32 scores -> fp16 probs; read+write bounded)
    softmax_kernel<<<BATCH * N_HEADS * SEQ, 256>>>(sc, p);

    // 10. ctx = probs @ Vt^T (fp16, causal K-trunc; C fp16)
    dim3 gC(D_HEAD / 128, SEQ / 128, BATCH * N_HEADS);
    gemm_h<0,2,false,true ><<<gC, 256, SMH>>>(p, vt, ctx, nullptr, nullptr,
        SEQ, SEQ, SEQ, D_MODEL,
        (long)N_HEADS * SEQ * SEQ, (long)SEQ * SEQ,
        (long)N_HEADS * D_HEAD * SEQ, (long)D_HEAD * SEQ,
        (long)SEQ * D_MODEL, (long)D_HEAD, N_HEADS);

    // 11. x2 = x + ctx @ wo (C fp32)
    dim3 gP(D_MODEL / 128, NROWS / 128, 1);
    gemm_h<2,0,false,false><<<gP, 256, SMH>>>(ctx, woT, x2, nullptr, x,
        D_MODEL, D_MODEL, D_MODEL, D_MODEL, 0, 0, 0, 0, 0, 0, 1);

    // 12. LayerNorm 2 (emits fp16)
    layernorm_kernel<<<NROWS, 256>>>(x2, lns, lno, xn2);

    // 13. h = gelu(xn2 @ w_in + b_in) (C fp16)
    dim3 gF(D_FF / 128, NROWS / 128, 1);
    gemm_h<1,2,false,false><<<gF, 256, SMH>>>(xn2, winT, hbuf, b_in, nullptr,
        D_MODEL, D_MODEL, D_MODEL, D_FF, 0, 0, 0, 0, 0, 0, 1);

    // 14. out = x2 + h @ w_out + b_out (C fp32)
    gemm_h<3,0,false,false><<<gP, 256, SMH>>>(hbuf, wouT, out, b_out, x2,
        D_FF, D_FF, D_FF, D_MODEL, 0, 0, 0, 0, 0, 0, 1);
}

// round 14
// speedup vs baseline: 1.0941x; 1.0341x over previous
#include <cuda_runtime.h>
#include <cuda_fp16.h>
#include <cstdint>
#include <math.h>

#define D_MODEL 4096
#define N_HEADS 16
#define D_HEAD  256
#define ROTARY  64
#define D_FF    16384
#define BATCH   2
#define SEQ     2048
#define NROWS   (BATCH*SEQ)   /* 4096 */

#define STAGES 3
/* fp16 GEMM: BK=64 halfs, row stride 72 halfs = 144B (LDSM conflict-free) */
#define ROWB 144
#define STGB (128 * ROWB)          /* per-stage bytes per operand: 18,432 */
#define SMH  (STAGES * 2 * STGB)   /* 110,592 */

// ---------------------------------------------------------------------------
// Scratch (static device globals; no allocation allowed)
// ---------------------------------------------------------------------------
__device__ __align__(16) __half g_xn [(size_t)NROWS * D_MODEL];
__device__ __align__(16) __half g_xn2[(size_t)NROWS * D_MODEL];
__device__ __align__(16) __half g_q  [(size_t)NROWS * D_MODEL];
__device__ __align__(16) __half g_k  [(size_t)NROWS * D_MODEL];
__device__ __align__(16) __half g_v  [(size_t)NROWS * D_MODEL];
__device__ __align__(16) __half g_vt [(size_t)NROWS * D_MODEL];   // per-head V^T
__device__ __align__(16) __half g_ctx[(size_t)NROWS * D_MODEL];
__device__ __align__(16) __half g_h  [(size_t)NROWS * D_FF];
__device__ __align__(16) __half g_p  [(size_t)BATCH * N_HEADS * SEQ * SEQ]; // 256 MB probs
__device__ __align__(16) __half g_sc [(size_t)BATCH * N_HEADS * SEQ * SEQ]; // 256 MB scores (fp16)
__device__ __align__(16) __half g_wh [(size_t)201326592];                   // 384 MB W^T fp16
__device__ __align__(16) float  g_x2 [(size_t)NROWS * D_MODEL];

// ---------------------------------------------------------------------------
// Helpers
// ---------------------------------------------------------------------------
__device__ __forceinline__ float gelu_f(float x) {
    return 0.5f * x * (1.0f + tanhf(0.7978845608028654f * (x + 0.044715f * x * x * x)));
}
__device__ __forceinline__ void cp16(uint32_t dst, const void* src) {
    asm volatile("cp.async.cg.shared.global [%0], [%1], 16;\n" :: "r"(dst), "l"(src));
}
__device__ __forceinline__ void cp_commit() {
    asm volatile("cp.async.commit_group;\n" ::: "memory");
}
__device__ __forceinline__ void cp_wait1() {
    asm volatile("cp.async.wait_group 1;\n" ::: "memory");
}
__device__ __forceinline__ void ldsm4(uint32_t& r0, uint32_t& r1, uint32_t& r2, uint32_t& r3,
                                      uint32_t addr) {
    asm volatile("ldmatrix.sync.aligned.m8n8.x4.shared.b16 {%0,%1,%2,%3}, [%4];"
                 : "=r"(r0), "=r"(r1), "=r"(r2), "=r"(r3) : "r"(addr));
}

// ---------------------------------------------------------------------------
// Weight transpose + fp16 convert: out[c][r] = half(in[r][c])
// ---------------------------------------------------------------------------
__global__ void transpose4_kernel(const float* __restrict__ w0, const float* __restrict__ w1,
                                  const float* __restrict__ w2, const float* __restrict__ w3,
                                  __half* __restrict__ o0, __half* __restrict__ o1,
                                  __half* __restrict__ o2, __half* __restrict__ o3)
{
    __shared__ float tile[32][33];
    const float* in; __half* out;
    switch (blockIdx.z) {
        case 0: in = w0; out = o0; break;
        case 1: in = w1; out = o1; break;
        case 2: in = w2; out = o2; break;
        default: in = w3; out = o3; break;
    }
    int x = blockIdx.x * 32 + threadIdx.x;
    int y = blockIdx.y * 32 + threadIdx.y;
#pragma unroll
    for (int j = 0; j < 32; j += 8)
        tile[threadIdx.y + j][threadIdx.x] = in[(size_t)(y + j) * 4096 + x];
    __syncthreads();
    x = blockIdx.y * 32 + threadIdx.x;
    y = blockIdx.x * 32 + threadIdx.y;
#pragma unroll
    for (int j = 0; j < 32; j += 8)
        out[(size_t)(y + j) * 4096 + x] = __float2half_rn(tile[threadIdx.x][threadIdx.y + j]);
}

__global__ void transpose_rc_kernel(const float* __restrict__ in, __half* __restrict__ out,
                                    int R, int C)
{
    __shared__ float tile[32][33];
    int x = blockIdx.x * 32 + threadIdx.x;
    int y = blockIdx.y * 32 + threadIdx.y;
#pragma unroll
    for (int j = 0; j < 32; j += 8)
        tile[threadIdx.y + j][threadIdx.x] = in[(size_t)(y + j) * C + x];
    __syncthreads();
    x = blockIdx.y * 32 + threadIdx.x;
    y = blockIdx.x * 32 + threadIdx.y;
#pragma unroll
    for (int j = 0; j < 32; j += 8)
        out[(size_t)(y + j) * R + x] = __float2half_rn(tile[threadIdx.x][threadIdx.y + j]);
}

// V [bt][h*256+d] fp16  ->  Vt [(b*4096 + h*256 + d)][s] fp16 (k-contiguous per head)
__global__ void transpose_v_kernel(const __half* __restrict__ in, __half* __restrict__ out)
{
    __shared__ __half tile[32][33];
    int x = blockIdx.x * 32 + threadIdx.x;    // dmodel col
    int y = blockIdx.y * 32 + threadIdx.y;    // bt row
#pragma unroll
    for (int j = 0; j < 32; j += 8)
        tile[threadIdx.y + j][threadIdx.x] = in[(size_t)(y + j) * D_MODEL + x];
    __syncthreads();
    int d0 = blockIdx.x * 32 + threadIdx.y;   // dmodel index base
    int yo = blockIdx.y * 32 + threadIdx.x;   // bt index
    int b = yo >> 11, s = yo & (SEQ - 1);
#pragma unroll
    for (int j = 0; j < 32; j += 8) {
        int d = d0 + j;
        out[((size_t)(b * D_MODEL + d)) * SEQ + s] = tile[threadIdx.x][threadIdx.y + j];
    }
}

// ---------------------------------------------------------------------------
// LayerNorm: one block per row; emits fp16
// ---------------------------------------------------------------------------
__global__ void layernorm_kernel(const float* __restrict__ x,
                                 const float* __restrict__ scale,
                                 const float* __restrict__ offset,
                                 __half* __restrict__ out)
{
    int row = blockIdx.x;
    const float4* xr = reinterpret_cast<const float4*>(x + (size_t)row * D_MODEL);
    float4 vals[4];
    float s = 0.f, sq = 0.f;
#pragma unroll
    for (int p = 0; p < 4; p++) {
        float4 v = xr[threadIdx.x + p * 256];
        vals[p] = v;
        s  += v.x + v.y + v.z + v.w;
        sq += v.x*v.x + v.y*v.y + v.z*v.z + v.w*v.w;
    }
    __shared__ float shm[64];
#pragma unroll
    for (int o = 16; o > 0; o >>= 1) {
        s  += __shfl_xor_sync(0xffffffffu, s,  o);
        sq += __shfl_xor_sync(0xffffffffu, sq, o);
    }
    int w = threadIdx.x >> 5;
    if ((threadIdx.x & 31) == 0) { shm[w] = s; shm[w + 32] = sq; }
    __syncthreads();
    if (threadIdx.x < 32) {
        float a = (threadIdx.x < 8) ? shm[threadIdx.x]      : 0.f;
        float b = (threadIdx.x < 8) ? shm[32 + threadIdx.x] : 0.f;
#pragma unroll
        for (int o = 4; o > 0; o >>= 1) {
            a += __shfl_xor_sync(0xffffffffu, a, o);
            b += __shfl_xor_sync(0xffffffffu, b, o);
        }
        if (threadIdx.x == 0) { shm[0] = a; shm[1] = b; }
    }
    __syncthreads();
    float mean = shm[0] * (1.0f / D_MODEL);
    float var  = shm[1] * (1.0f / D_MODEL) - mean * mean;
    float inv  = rsqrtf(var + 1e-5f);
    const float4* sc4 = reinterpret_cast<const float4*>(scale);
    const float4* of4 = reinterpret_cast<const float4*>(offset);
    __half2* o2 = reinterpret_cast<__half2*>(out + (size_t)row * D_MODEL);
#pragma unroll
    for (int p = 0; p < 4; p++) {
        int i = threadIdx.x + p * 256;
        float4 v = vals[p], g = sc4[i], b = of4[i];
        o2[i * 2]     = __floats2half2_rn((v.x - mean) * inv * g.x + b.x,
                                          (v.y - mean) * inv * g.y + b.y);
        o2[i * 2 + 1] = __floats2half2_rn((v.z - mean) * inv * g.z + b.z,
                                          (v.w - mean) * inv * g.w + b.w);
    }
}

// ---------------------------------------------------------------------------
// RoPE on fp16 q, k (compute fp32, store fp16)
// ---------------------------------------------------------------------------
__global__ void rope_kernel(__half* __restrict__ q, __half* __restrict__ k)
{
    const int HALF = ROTARY / 2;
    int idx = blockIdx.x * blockDim.x + threadIdx.x;
    int total = NROWS * N_HEADS * HALF;
    if (idx >= total) return;
    int i  = idx % HALF;
    int h  = (idx / HALF) % N_HEADS;
    int bt = idx / (HALF * N_HEADS);
    int t  = bt % SEQ;

    float inv_freq = powf(10000.0f, -(float)i / (float)HALF);
    float fr = (float)t * inv_freq;
    float sn, cs;
    sincosf(fr, &sn, &cs);

    size_t base = (size_t)bt * D_MODEL + (size_t)h * D_HEAD + 2 * i;
    __half2* qp = reinterpret_cast<__half2*>(q + base);
    __half2* kp = reinterpret_cast<__half2*>(k + base);
    float2 qv = __half22float2(*qp);
    float2 kv = __half22float2(*kp);
    *qp = __floats2half2_rn(qv.x * cs - qv.y * sn, qv.y * cs + qv.x * sn);
    *kp = __floats2half2_rn(kv.x * cs - kv.y * sn, kv.y * cs + kv.x * sn);
}

// ---------------------------------------------------------------------------
// Causal softmax: fp16 scores -> fp16 probs.  Skips chunks entirely beyond
// the causal bound on BOTH read and write.
// ---------------------------------------------------------------------------
__global__ void softmax_kernel(const __half* __restrict__ scores, __half* __restrict__ probs)
{
    size_t r = blockIdx.x;
    int t = blockIdx.x % SEQ;
    const __half* row = scores + r * SEQ;
    __half* prow = probs + r * SEQ;
    const float sc = 1.0f / 16.0f;
    int bound = ((t >> 7) + 1) << 7;

    float v[8];
    float mx = -1e30f;
#pragma unroll
    for (int j = 0; j < 8; j++) {
        int col = threadIdx.x + j * 256;
        float xv = -1e30f;
        if (j * 256 <= t) {                       // chunk intersects causal region
            float raw = __half2float(row[col]);
            if (col <= t) xv = raw * sc;
        }
        v[j] = xv;
        mx = fmaxf(mx, xv);
    }
    __shared__ float shm[32];
#pragma unroll
    for (int o = 16; o > 0; o >>= 1) mx = fmaxf(mx, __shfl_xor_sync(0xffffffffu, mx, o));
    if ((threadIdx.x & 31) == 0) shm[threadIdx.x >> 5] = mx;
    __syncthreads();
    if (threadIdx.x < 32) {
        float m = (threadIdx.x < 8) ? shm[threadIdx.x] : -1e30f;
#pragma unroll
        for (int o = 4; o > 0; o >>= 1) m = fmaxf(m, __shfl_xor_sync(0xffffffffu, m, o));
        if (threadIdx.x == 0) shm[0] = m;
    }
    __syncthreads();
    mx = shm[0];
    __syncthreads();

    float s = 0.f;
#pragma unroll
    for (int j = 0; j < 8; j++) { float e = expf(v[j] - mx); v[j] = e; s += e; }
#pragma unroll
    for (int o = 16; o > 0; o >>= 1) s += __shfl_xor_sync(0xffffffffu, s, o);
    if ((threadIdx.x & 31) == 0) shm[threadIdx.x >> 5] = s;
    __syncthreads();
    if (threadIdx.x < 32) {
        float a = (threadIdx.x < 8) ? shm[threadIdx.x] : 0.f;
#pragma unroll
        for (int o = 4; o > 0; o >>= 1) a += __shfl_xor_sync(0xffffffffu, a, o);
        if (threadIdx.x == 0) shm[0] = a;
    }
    __syncthreads();
    float inv = 1.0f / shm[0];
#pragma unroll
    for (int j = 0; j < 8; j++) {
        if (j * 256 < bound)
            prow[threadIdx.x + j * 256] = __float2half_rn(v[j] * inv);
    }
}

// ---------------------------------------------------------------------------
// FP16 tensor-core GEMM: C[M,N] = A[M,K] @ Bt[N,K]^T (+epi)
//   128x128 CTA tile, __launch_bounds__(256,2) -> 2 CTAs/SM (16 warps).
//   m16n8k16 MMA via ldmatrix.b16; cp.async 3-stage, BK=64 halfs.
//   (R9-proven structure: next-next loads issued AFTER the MMA block.)
//   EPI: 0 none | 1 bias+gelu | 2 +Res | 3 bias+Res
//   OUT: 0 f32 | 2 fp16
//   CSKIP: causal tile skip (scores).  CKT: causal K truncation (ctx).
// ---------------------------------------------------------------------------
template<int EPI, int OUT, bool CSKIP, bool CKT>
__global__ void __launch_bounds__(256, 2)
gemm_h(const __half* __restrict__ A, const __half* __restrict__ Bt,
       void* __restrict__ Cv, const float* __restrict__ bias,
       const float* __restrict__ Res,
       int K, int lda, int ldb, int ldc,
       long sAb, long sAh, long sBb, long sBh, long sCb, long sCh, int Hb)
{
    int m0 = blockIdx.y * 128;
    int n0 = blockIdx.x * 128;
    if (CSKIP) { if (n0 > m0 + 127) return; }

    int z = blockIdx.z;
    int b = z / Hb, hh = z % Hb;
    A  += (size_t)b * sAb + (size_t)hh * sAh;
    Bt += (size_t)b * sBb + (size_t)hh * sBh;
    float*  Cf = reinterpret_cast<float*>(Cv)  + (size_t)b * sCb + (size_t)hh * sCh;
    __half* Ch = reinterpret_cast<__half*>(Cv) + (size_t)b * sCb + (size_t)hh * sCh;

    extern __shared__ char smem_dyn[];
    uint32_t aBase = (uint32_t)__cvta_generic_to_shared(smem_dyn);
    uint32_t bBase = aBase + STAGES * STGB;

    int tid = threadIdx.x;
    int lane = tid & 31, warp = tid >> 5;
    int wm = warp & 3, wn = warp >> 2;
    int g  = lane >> 2, tg = lane & 3;

    float acc[2][8][4] = {};

    int KT = K >> 6;
    if (CKT) { int lim = (m0 + 128) >> 6; if (lim < KT) KT = lim; }

    int lc = tid & 7, lr = tid >> 3;       // load: 8 chunks/row, 32 rows/pass

    auto loadTile = [&](int kt, int s) {
        const __half* ap = A + (size_t)m0 * lda + (size_t)kt * 64;
#pragma unroll
        for (int p = 0; p < 4; p++) {
            int row = lr + p * 32;
            cp16(aBase + (uint32_t)(s * STGB + row * ROWB + lc * 16),
                 ap + (size_t)row * lda + lc * 8);
        }
        const __half* bp = Bt + (size_t)n0 * ldb + (size_t)kt * 64;
#pragma unroll
        for (int p = 0; p < 4; p++) {
            int row = lr + p * 32;
            cp16(bBase + (uint32_t)(s * STGB + row * ROWB + lc * 16),
                 bp + (size_t)row * ldb + lc * 8);
        }
    };

    loadTile(0, 0); cp_commit();
    if (KT > 1) loadTile(1, 1);
    cp_commit();

    int lane_row = (lane & 7) | (((lane >> 3) & 1) << 3);  // 0..15
    int lane_kb  = (lane >> 4) << 4;                        // 0 or 16 bytes
    uint32_t aoff0 = (uint32_t)((wm * 32 + lane_row) * ROWB + lane_kb);
    uint32_t boff0 = (uint32_t)((wn * 64 + lane_row) * ROWB + lane_kb);

    for (int kt = 0; kt < KT; kt++) {
        cp_wait1();
        __syncthreads();
        int s = kt % STAGES;
        uint32_t aS = aBase + (uint32_t)(s * STGB) + aoff0;
        uint32_t bS = bBase + (uint32_t)(s * STGB) + boff0;

#pragma unroll
        for (int kk = 0; kk < 4; kk++) {
            uint32_t af[2][4], bf[8][2];
            uint32_t kkb = kk * 32;
#pragma unroll
            for (int mt = 0; mt < 2; mt++)
                ldsm4(af[mt][0], af[mt][1], af[mt][2], af[mt][3],
                      aS + (uint32_t)(mt * 16 * ROWB) + kkb);
#pragma unroll
            for (int p = 0; p < 4; p++)
                ldsm4(bf[2*p][0], bf[2*p+1][0], bf[2*p][1], bf[2*p+1][1],
                      bS + (uint32_t)(p * 16 * ROWB) + kkb);
#pragma unroll
            for (int mt = 0; mt < 2; mt++)
#pragma unroll
                for (int nt = 0; nt < 8; nt++) {
                    asm volatile(
                        "mma.sync.aligned.m16n8k16.row.col.f32.f16.f16.f32 "
                        "{%0,%1,%2,%3}, {%4,%5,%6,%7}, {%8,%9}, {%0,%1,%2,%3};\n"
                        : "+f"(acc[mt][nt][0]), "+f"(acc[mt][nt][1]),
                          "+f"(acc[mt][nt][2]), "+f"(acc[mt][nt][3])
                        : "r"(af[mt][0]), "r"(af[mt][1]), "r"(af[mt][2]), "r"(af[mt][3]),
                          "r"(bf[nt][0]), "r"(bf[nt][1]));
                }
        }

        if (kt + 2 < KT) loadTile(kt + 2, (kt + 2) % STAGES);
        cp_commit();
    }

    // Epilogue
#pragma unroll
    for (int mt = 0; mt < 2; mt++) {
#pragma unroll
        for (int nt = 0; nt < 8; nt++) {
            int row0 = m0 + wm * 32 + mt * 16 + g;
            int col  = n0 + wn * 64 + nt * 8 + 2 * tg;
#pragma unroll
            for (int rr = 0; rr < 2; rr++) {
                int row = row0 + rr * 8;
                float v0 = acc[mt][nt][rr * 2 + 0];
                float v1 = acc[mt][nt][rr * 2 + 1];
                if (EPI == 1) {
                    v0 = gelu_f(v0 + bias[col]);
                    v1 = gelu_f(v1 + bias[col + 1]);
                } else if (EPI == 2) {
                    float2 rv = *reinterpret_cast<const float2*>(&Res[(size_t)row * ldc + col]);
                    v0 += rv.x; v1 += rv.y;
                } else if (EPI == 3) {
                    float2 rv = *reinterpret_cast<const float2*>(&Res[(size_t)row * ldc + col]);
                    v0 += bias[col] + rv.x; v1 += bias[col + 1] + rv.y;
                }
                if (OUT == 2) {
                    *reinterpret_cast<__half2*>(&Ch[(size_t)row * ldc + col]) =
                        __floats2half2_rn(v0, v1);
                } else {
                    float2 ov; ov.x = v0; ov.y = v1;
                    *reinterpret_cast<float2*>(&Cf[(size_t)row * ldc + col]) = ov;
                }
            }
        }
    }
}

// ---------------------------------------------------------------------------
// Launch
// ---------------------------------------------------------------------------
extern "C" void kernel_launch(void* const* d_in, const int* in_sizes, int n_in,
                              void* d_out, int out_size)
{
    (void)in_sizes; (void)n_in; (void)out_size;
    const float* x     = (const float*)d_in[0];
    const float* lns   = (const float*)d_in[1];
    const float* lno   = (const float*)d_in[2];
    const float* wq    = (const float*)d_in[3];
    const float* wk    = (const float*)d_in[4];
    const float* wv    = (const float*)d_in[5];
    const float* wo    = (const float*)d_in[6];
    const float* w_in  = (const float*)d_in[7];
    const float* b_in  = (const float*)d_in[8];
    const float* w_out = (const float*)d_in[9];
    const float* b_out = (const float*)d_in[10];
    float* out = (float*)d_out;

    __half *xn, *xn2, *q, *k, *v, *vt, *ctx, *hbuf, *p, *sc, *wh;
    float *x2;
    cudaGetSymbolAddress((void**)&xn,   g_xn);
    cudaGetSymbolAddress((void**)&xn2,  g_xn2);
    cudaGetSymbolAddress((void**)&q,    g_q);
    cudaGetSymbolAddress((void**)&k,    g_k);
    cudaGetSymbolAddress((void**)&v,    g_v);
    cudaGetSymbolAddress((void**)&vt,   g_vt);
    cudaGetSymbolAddress((void**)&ctx,  g_ctx);
    cudaGetSymbolAddress((void**)&hbuf, g_h);
    cudaGetSymbolAddress((void**)&p,    g_p);
    cudaGetSymbolAddress((void**)&sc,   g_sc);
    cudaGetSymbolAddress((void**)&wh,   g_wh);
    cudaGetSymbolAddress((void**)&x2,   g_x2);

    const size_t WSZ = (size_t)D_MODEL * D_MODEL;
    __half* wqT  = wh;
    __half* wkT  = wh + WSZ;
    __half* wvT  = wh + 2 * WSZ;
    __half* woT  = wh + 3 * WSZ;
    __half* winT = wh + 4 * WSZ;                    // [D_FF, D_MODEL]
    __half* wouT = winT + (size_t)D_MODEL * D_FF;   // [D_MODEL, D_FF]

    cudaFuncSetAttribute(gemm_h<0,2,false,false>, cudaFuncAttributeMaxDynamicSharedMemorySize, SMH);
    cudaFuncSetAttribute(gemm_h<0,2,true ,false>, cudaFuncAttributeMaxDynamicSharedMemorySize, SMH);
    cudaFuncSetAttribute(gemm_h<0,2,false,true >, cudaFuncAttributeMaxDynamicSharedMemorySize, SMH);
    cudaFuncSetAttribute(gemm_h<2,0,false,false>, cudaFuncAttributeMaxDynamicSharedMemorySize, SMH);
    cudaFuncSetAttribute(gemm_h<1,2,false,false>, cudaFuncAttributeMaxDynamicSharedMemorySize, SMH);
    cudaFuncSetAttribute(gemm_h<3,0,false,false>, cudaFuncAttributeMaxDynamicSharedMemorySize, SMH);

    dim3 tb(32, 8);

    // 1-3. Transpose + fp16-convert all weights into [N,K]
    transpose4_kernel<<<dim3(128, 128, 4), tb>>>(wq, wk, wv, wo, wqT, wkT, wvT, woT);
    transpose_rc_kernel<<<dim3(D_FF / 32, D_MODEL / 32), tb>>>(w_in,  winT, D_MODEL, D_FF);
    transpose_rc_kernel<<<dim3(D_MODEL / 32, D_FF / 32), tb>>>(w_out, wouT, D_FF, D_MODEL);

    // 4. LayerNorm (emits fp16)
    layernorm_kernel<<<NROWS, 256>>>(x, lns, lno, xn);

    // 5-7. QKV projections (all fp16 out)
    dim3 gP(D_MODEL / 128, NROWS / 128, 1);
    gemm_h<0,2,false,false><<<gP, 256, SMH>>>(xn, wqT, q, nullptr, nullptr,
        D_MODEL, D_MODEL, D_MODEL, D_MODEL, 0, 0, 0, 0, 0, 0, 1);
    gemm_h<0,2,false,false><<<gP, 256, SMH>>>(xn, wkT, k, nullptr, nullptr,
        D_MODEL, D_MODEL, D_MODEL, D_MODEL, 0, 0, 0, 0, 0, 0, 1);
    gemm_h<0,2,false,false><<<gP, 256, SMH>>>(xn, wvT, v, nullptr, nullptr,
        D_MODEL, D_MODEL, D_MODEL, D_MODEL, 0, 0, 0, 0, 0, 0, 1);

    // 8. RoPE (fp16)
    {
        int total = NROWS * N_HEADS * (ROTARY / 2);
        rope_kernel<<<(total + 255) / 256, 256>>>(q, k);
    }

    // 9. Per-head V transpose -> Vt (k-contiguous)
    transpose_v_kernel<<<dim3(D_MODEL / 32, NROWS / 32), tb>>>(v, vt);

    // 10. scores = q @ k^T (causal tile-skip, batched b,h; C fp16)
    dim3 gS(SEQ / 128, SEQ / 128, BATCH * N_HEADS);
    gemm_h<0,2,true ,false><<<gS, 256, SMH>>>(q, k, sc, nullptr, nullptr,
        D_HEAD, D_MODEL, D_MODEL, SEQ,
        (long)SEQ * D_MODEL, (long)D_HEAD,
        (long)SEQ * D_MODEL, (long)D_HEAD,
        (long)N_HEADS * SEQ * SEQ, (long)SEQ * SEQ, N_HEADS);

    // 11. causal softmax (fp16 scores -> fp16 probs; read+write bounded)
    softmax_kernel<<<BATCH * N_HEADS * SEQ, 256>>>(sc, p);

    // 12. ctx = probs @ Vt^T (fp16, causal K-trunc; C fp16)
    dim3 gC(D_HEAD / 128, SEQ / 128, BATCH * N_HEADS);
    gemm_h<0,2,false,true ><<<gC, 256, SMH>>>(p, vt, ctx, nullptr, nullptr,
        SEQ, SEQ, SEQ, D_MODEL,
        (long)N_HEADS * SEQ * SEQ, (long)SEQ * SEQ,
        (long)N_HEADS * D_HEAD * SEQ, (long)D_HEAD * SEQ,
        (long)SEQ * D_MODEL, (long)D_HEAD, N_HEADS);

    // 13. x2 = x + ctx @ wo (C fp32)
    gemm_h<2,0,false,false><<<gP, 256, SMH>>>(ctx, woT, x2, nullptr, x,
        D_MODEL, D_MODEL, D_MODEL, D_MODEL, 0, 0, 0, 0, 0, 0, 1);

    // 14. LayerNorm 2 (emits fp16)
    layernorm_kernel<<<NROWS, 256>>>(x2, lns, lno, xn2);

    // 15. h = gelu(xn2 @ w_in + b_in) (C fp16)
    dim3 gF(D_FF / 128, NROWS / 128, 1);
    gemm_h<1,2,false,false><<<gF, 256, SMH>>>(xn2, winT, hbuf, b_in, nullptr,
        D_MODEL, D_MODEL, D_MODEL, D_FF, 0, 0, 0, 0, 0, 0, 1);

    // 16. out = x2 + h @ w_out + b_out (C fp32)
    gemm_h<3,0,false,false><<<gP, 256, SMH>>>(hbuf, wouT, out, b_out, x2,
        D_FF, D_FF, D_FF, D_MODEL, 0, 0, 0, 0, 0, 0, 1);
}

// round 15
// speedup vs baseline: 1.0962x; 1.0020x over previous
#include <cuda_runtime.h>
#include <cuda_fp16.h>
#include <cstdint>
#include <math.h>

#define D_MODEL 4096
#define N_HEADS 16
#define D_HEAD  256
#define ROTARY  64
#define D_FF    16384
#define BATCH   2
#define SEQ     2048
#define NROWS   (BATCH*SEQ)   /* 4096 */

#define STAGES 3
/* fp16 GEMM: BK=64 halfs, row stride 72 halfs = 144B (LDSM conflict-free) */
#define ROWB 144
#define STGB (128 * ROWB)          /* per-stage bytes per operand: 18,432 */
#define SMH  (STAGES * 2 * STGB)   /* 110,592 */

// ---------------------------------------------------------------------------
// Scratch (static device globals; no allocation allowed)
// ---------------------------------------------------------------------------
__device__ __align__(16) __half g_xn [(size_t)NROWS * D_MODEL];
__device__ __align__(16) __half g_xn2[(size_t)NROWS * D_MODEL];
__device__ __align__(16) __half g_q  [(size_t)NROWS * D_MODEL];
__device__ __align__(16) __half g_k  [(size_t)NROWS * D_MODEL];
__device__ __align__(16) __half g_v  [(size_t)NROWS * D_MODEL];
__device__ __align__(16) __half g_vt [(size_t)NROWS * D_MODEL];   // per-head V^T
__device__ __align__(16) __half g_ctx[(size_t)NROWS * D_MODEL];
__device__ __align__(16) __half g_h  [(size_t)NROWS * D_FF];
__device__ __align__(16) __half g_p  [(size_t)BATCH * N_HEADS * SEQ * SEQ]; // 256 MB probs
__device__ __align__(16) __half g_sc [(size_t)BATCH * N_HEADS * SEQ * SEQ]; // 256 MB scores (fp16)
__device__ __align__(16) __half g_wh [(size_t)201326592];                   // 384 MB W^T fp16
__device__ __align__(16) float  g_x2 [(size_t)NROWS * D_MODEL];

// ---------------------------------------------------------------------------
// Helpers
// ---------------------------------------------------------------------------
__device__ __forceinline__ float gelu_f(float x) {
    return 0.5f * x * (1.0f + tanhf(0.7978845608028654f * (x + 0.044715f * x * x * x)));
}
__device__ __forceinline__ void cp16(uint32_t dst, const void* src) {
    asm volatile("cp.async.cg.shared.global [%0], [%1], 16;\n" :: "r"(dst), "l"(src));
}
__device__ __forceinline__ void cp_commit() {
    asm volatile("cp.async.commit_group;\n" ::: "memory");
}
__device__ __forceinline__ void cp_wait1() {
    asm volatile("cp.async.wait_group 1;\n" ::: "memory");
}
__device__ __forceinline__ void ldsm4(uint32_t& r0, uint32_t& r1, uint32_t& r2, uint32_t& r3,
                                      uint32_t addr) {
    asm volatile("ldmatrix.sync.aligned.m8n8.x4.shared.b16 {%0,%1,%2,%3}, [%4];"
                 : "=r"(r0), "=r"(r1), "=r"(r2), "=r"(r3) : "r"(addr));
}

// ---------------------------------------------------------------------------
// Weight transpose + fp16 convert: out[c][r] = half(in[r][c])
// ---------------------------------------------------------------------------
__global__ void transpose4_kernel(const float* __restrict__ w0, const float* __restrict__ w1,
                                  const float* __restrict__ w2, const float* __restrict__ w3,
                                  __half* __restrict__ o0, __half* __restrict__ o1,
                                  __half* __restrict__ o2, __half* __restrict__ o3)
{
    __shared__ float tile[32][33];
    const float* in; __half* out;
    switch (blockIdx.z) {
        case 0: in = w0; out = o0; break;
        case 1: in = w1; out = o1; break;
        case 2: in = w2; out = o2; break;
        default: in = w3; out = o3; break;
    }
    int x = blockIdx.x * 32 + threadIdx.x;
    int y = blockIdx.y * 32 + threadIdx.y;
#pragma unroll
    for (int j = 0; j < 32; j += 8)
        tile[threadIdx.y + j][threadIdx.x] = in[(size_t)(y + j) * 4096 + x];
    __syncthreads();
    x = blockIdx.y * 32 + threadIdx.x;
    y = blockIdx.x * 32 + threadIdx.y;
#pragma unroll
    for (int j = 0; j < 32; j += 8)
        out[(size_t)(y + j) * 4096 + x] = __float2half_rn(tile[threadIdx.x][threadIdx.y + j]);
}

__global__ void transpose_rc_kernel(const float* __restrict__ in, __half* __restrict__ out,
                                    int R, int C)
{
    __shared__ float tile[32][33];
    int x = blockIdx.x * 32 + threadIdx.x;
    int y = blockIdx.y * 32 + threadIdx.y;
#pragma unroll
    for (int j = 0; j < 32; j += 8)
        tile[threadIdx.y + j][threadIdx.x] = in[(size_t)(y + j) * C + x];
    __syncthreads();
    x = blockIdx.y * 32 + threadIdx.x;
    y = blockIdx.x * 32 + threadIdx.y;
#pragma unroll
    for (int j = 0; j < 32; j += 8)
        out[(size_t)(y + j) * R + x] = __float2half_rn(tile[threadIdx.x][threadIdx.y + j]);
}

// V [bt][h*256+d] fp16  ->  Vt [(b*4096 + h*256 + d)][s] fp16 (k-contiguous per head)
__global__ void transpose_v_kernel(const __half* __restrict__ in, __half* __restrict__ out)
{
    __shared__ __half tile[32][33];
    int x = blockIdx.x * 32 + threadIdx.x;    // dmodel col
    int y = blockIdx.y * 32 + threadIdx.y;    // bt row
#pragma unroll
    for (int j = 0; j < 32; j += 8)
        tile[threadIdx.y + j][threadIdx.x] = in[(size_t)(y + j) * D_MODEL + x];
    __syncthreads();
    int d0 = blockIdx.x * 32 + threadIdx.y;   // dmodel index base
    int yo = blockIdx.y * 32 + threadIdx.x;   // bt index
    int b = yo >> 11, s = yo & (SEQ - 1);
#pragma unroll
    for (int j = 0; j < 32; j += 8) {
        int d = d0 + j;
        out[((size_t)(b * D_MODEL + d)) * SEQ + s] = tile[threadIdx.x][threadIdx.y + j];
    }
}

// ---------------------------------------------------------------------------
// LayerNorm: one block per row; emits fp16
// ---------------------------------------------------------------------------
__global__ void layernorm_kernel(const float* __restrict__ x,
                                 const float* __restrict__ scale,
                                 const float* __restrict__ offset,
                                 __half* __restrict__ out)
{
    int row = blockIdx.x;
    const float4* xr = reinterpret_cast<const float4*>(x + (size_t)row * D_MODEL);
    float4 vals[4];
    float s = 0.f, sq = 0.f;
#pragma unroll
    for (int p = 0; p < 4; p++) {
        float4 v = xr[threadIdx.x + p * 256];
        vals[p] = v;
        s  += v.x + v.y + v.z + v.w;
        sq += v.x*v.x + v.y*v.y + v.z*v.z + v.w*v.w;
    }
    __shared__ float shm[64];
#pragma unroll
    for (int o = 16; o > 0; o >>= 1) {
        s  += __shfl_xor_sync(0xffffffffu, s,  o);
        sq += __shfl_xor_sync(0xffffffffu, sq, o);
    }
    int w = threadIdx.x >> 5;
    if ((threadIdx.x & 31) == 0) { shm[w] = s; shm[w + 32] = sq; }
    __syncthreads();
    if (threadIdx.x < 32) {
        float a = (threadIdx.x < 8) ? shm[threadIdx.x]      : 0.f;
        float b = (threadIdx.x < 8) ? shm[32 + threadIdx.x] : 0.f;
#pragma unroll
        for (int o = 4; o > 0; o >>= 1) {
            a += __shfl_xor_sync(0xffffffffu, a, o);
            b += __shfl_xor_sync(0xffffffffu, b, o);
        }
        if (threadIdx.x == 0) { shm[0] = a; shm[1] = b; }
    }
    __syncthreads();
    float mean = shm[0] * (1.0f / D_MODEL);
    float var  = shm[1] * (1.0f / D_MODEL) - mean * mean;
    float inv  = rsqrtf(var + 1e-5f);
    const float4* sc4 = reinterpret_cast<const float4*>(scale);
    const float4* of4 = reinterpret_cast<const float4*>(offset);
    __half2* o2 = reinterpret_cast<__half2*>(out + (size_t)row * D_MODEL);
#pragma unroll
    for (int p = 0; p < 4; p++) {
        int i = threadIdx.x + p * 256;
        float4 v = vals[p], g = sc4[i], b = of4[i];
        o2[i * 2]     = __floats2half2_rn((v.x - mean) * inv * g.x + b.x,
                                          (v.y - mean) * inv * g.y + b.y);
        o2[i * 2 + 1] = __floats2half2_rn((v.z - mean) * inv * g.z + b.z,
                                          (v.w - mean) * inv * g.w + b.w);
    }
}

// ---------------------------------------------------------------------------
// RoPE on fp16 q, k (compute fp32, store fp16)
// ---------------------------------------------------------------------------
__global__ void rope_kernel(__half* __restrict__ q, __half* __restrict__ k)
{
    const int HALF = ROTARY / 2;
    int idx = blockIdx.x * blockDim.x + threadIdx.x;
    int total = NROWS * N_HEADS * HALF;
    if (idx >= total) return;
    int i  = idx % HALF;
    int h  = (idx / HALF) % N_HEADS;
    int bt = idx / (HALF * N_HEADS);
    int t  = bt % SEQ;

    float inv_freq = powf(10000.0f, -(float)i / (float)HALF);
    float fr = (float)t * inv_freq;
    float sn, cs;
    sincosf(fr, &sn, &cs);

    size_t base = (size_t)bt * D_MODEL + (size_t)h * D_HEAD + 2 * i;
    __half2* qp = reinterpret_cast<__half2*>(q + base);
    __half2* kp = reinterpret_cast<__half2*>(k + base);
    float2 qv = __half22float2(*qp);
    float2 kv = __half22float2(*kp);
    *qp = __floats2half2_rn(qv.x * cs - qv.y * sn, qv.y * cs + qv.x * sn);
    *kp = __floats2half2_rn(kv.x * cs - kv.y * sn, kv.y * cs + kv.x * sn);
}

// ---------------------------------------------------------------------------
// Causal softmax: fp16 scores -> fp16 probs.  Skips chunks entirely beyond
// the causal bound on BOTH read and write.
// ---------------------------------------------------------------------------
__global__ void softmax_kernel(const __half* __restrict__ scores, __half* __restrict__ probs)
{
    size_t r = blockIdx.x;
    int t = blockIdx.x % SEQ;
    const __half* row = scores + r * SEQ;
    __half* prow = probs + r * SEQ;
    const float sc = 1.0f / 16.0f;
    int bound = ((t >> 7) + 1) << 7;

    float v[8];
    float mx = -1e30f;
#pragma unroll
    for (int j = 0; j < 8; j++) {
        int col = threadIdx.x + j * 256;
        float xv = -1e30f;
        if (j * 256 <= t) {                       // chunk intersects causal region
            float raw = __half2float(row[col]);
            if (col <= t) xv = raw * sc;
        }
        v[j] = xv;
        mx = fmaxf(mx, xv);
    }
    __shared__ float shm[32];
#pragma unroll
    for (int o = 16; o > 0; o >>= 1) mx = fmaxf(mx, __shfl_xor_sync(0xffffffffu, mx, o));
    if ((threadIdx.x & 31) == 0) shm[threadIdx.x >> 5] = mx;
    __syncthreads();
    if (threadIdx.x < 32) {
        float m = (threadIdx.x < 8) ? shm[threadIdx.x] : -1e30f;
#pragma unroll
        for (int o = 4; o > 0; o >>= 1) m = fmaxf(m, __shfl_xor_sync(0xffffffffu, m, o));
        if (threadIdx.x == 0) shm[0] = m;
    }
    __syncthreads();
    mx = shm[0];
    __syncthreads();

    float s = 0.f;
#pragma unroll
    for (int j = 0; j < 8; j++) { float e = expf(v[j] - mx); v[j] = e; s += e; }
#pragma unroll
    for (int o = 16; o > 0; o >>= 1) s += __shfl_xor_sync(0xffffffffu, s, o);
    if ((threadIdx.x & 31) == 0) shm[threadIdx.x >> 5] = s;
    __syncthreads();
    if (threadIdx.x < 32) {
        float a = (threadIdx.x < 8) ? shm[threadIdx.x] : 0.f;
#pragma unroll
        for (int o = 4; o > 0; o >>= 1) a += __shfl_xor_sync(0xffffffffu, a, o);
        if (threadIdx.x == 0) shm[0] = a;
    }
    __syncthreads();
    float inv = 1.0f / shm[0];
#pragma unroll
    for (int j = 0; j < 8; j++) {
        if (j * 256 < bound)
            prow[threadIdx.x + j * 256] = __float2half_rn(v[j] * inv);
    }
}

// ---------------------------------------------------------------------------
// FP16 tensor-core GEMM: C[M,N] = A[M,K] @ Bt[N,K]^T (+epi)
//   128x128 CTA tile, __launch_bounds__(256,2) -> 2 CTAs/SM (16 warps).
//   m16n8k16 MMA via ldmatrix.b16; cp.async 3-stage, BK=64 halfs.
//   (R9-proven structure: next-next loads issued AFTER the MMA block.)
//   EPI: 0 none | 1 bias+gelu | 2 +Res | 3 bias+Res
//   OUT: 0 f32 | 2 fp16
//   CSKIP: causal tile skip (scores).  CKT: causal K truncation (ctx).
// ---------------------------------------------------------------------------
template<int EPI, int OUT, bool CSKIP, bool CKT>
__global__ void __launch_bounds__(256, 2)
gemm_h(const __half* __restrict__ A, const __half* __restrict__ Bt,
       void* __restrict__ Cv, const float* __restrict__ bias,
       const float* __restrict__ Res,
       int K, int lda, int ldb, int ldc,
       long sAb, long sAh, long sBb, long sBh, long sCb, long sCh, int Hb)
{
    int m0 = blockIdx.y * 128;
    int n0 = blockIdx.x * 128;
    if (CSKIP) { if (n0 > m0 + 127) return; }

    int z = blockIdx.z;
    int b = z / Hb, hh = z % Hb;
    A  += (size_t)b * sAb + (size_t)hh * sAh;
    Bt += (size_t)b * sBb + (size_t)hh * sBh;
    float*  Cf = reinterpret_cast<float*>(Cv)  + (size_t)b * sCb + (size_t)hh * sCh;
    __half* Ch = reinterpret_cast<__half*>(Cv) + (size_t)b * sCb + (size_t)hh * sCh;

    extern __shared__ char smem_dyn[];
    uint32_t aBase = (uint32_t)__cvta_generic_to_shared(smem_dyn);
    uint32_t bBase = aBase + STAGES * STGB;

    int tid = threadIdx.x;
    int lane = tid & 31, warp = tid >> 5;
    int wm = warp & 3, wn = warp >> 2;
    int g  = lane >> 2, tg = lane & 3;

    float acc[2][8][4] = {};

    int KT = K >> 6;
    if (CKT) { int lim = (m0 + 128) >> 6; if (lim < KT) KT = lim; }

    int lc = tid & 7, lr = tid >> 3;       // load: 8 chunks/row, 32 rows/pass

    auto loadTile = [&](int kt, int s) {
        const __half* ap = A + (size_t)m0 * lda + (size_t)kt * 64;
#pragma unroll
        for (int p = 0; p < 4; p++) {
            int row = lr + p * 32;
            cp16(aBase + (uint32_t)(s * STGB + row * ROWB + lc * 16),
                 ap + (size_t)row * lda + lc * 8);
        }
        const __half* bp = Bt + (size_t)n0 * ldb + (size_t)kt * 64;
#pragma unroll
        for (int p = 0; p < 4; p++) {
            int row = lr + p * 32;
            cp16(bBase + (uint32_t)(s * STGB + row * ROWB + lc * 16),
                 bp + (size_t)row * ldb + lc * 8);
        }
    };

    loadTile(0, 0); cp_commit();
    if (KT > 1) loadTile(1, 1);
    cp_commit();

    int lane_row = (lane & 7) | (((lane >> 3) & 1) << 3);  // 0..15
    int lane_kb  = (lane >> 4) << 4;                        // 0 or 16 bytes
    uint32_t aoff0 = (uint32_t)((wm * 32 + lane_row) * ROWB + lane_kb);
    uint32_t boff0 = (uint32_t)((wn * 64 + lane_row) * ROWB + lane_kb);

    for (int kt = 0; kt < KT; kt++) {
        cp_wait1();
        __syncthreads();
        int s = kt % STAGES;
        uint32_t aS = aBase + (uint32_t)(s * STGB) + aoff0;
        uint32_t bS = bBase + (uint32_t)(s * STGB) + boff0;

#pragma unroll
        for (int kk = 0; kk < 4; kk++) {
            uint32_t af[2][4], bf[8][2];
            uint32_t kkb = kk * 32;
#pragma unroll
            for (int mt = 0; mt < 2; mt++)
                ldsm4(af[mt][0], af[mt][1], af[mt][2], af[mt][3],
                      aS + (uint32_t)(mt * 16 * ROWB) + kkb);
#pragma unroll
            for (int p = 0; p < 4; p++)
                ldsm4(bf[2*p][0], bf[2*p+1][0], bf[2*p][1], bf[2*p+1][1],
                      bS + (uint32_t)(p * 16 * ROWB) + kkb);
#pragma unroll
            for (int mt = 0; mt < 2; mt++)
#pragma unroll
                for (int nt = 0; nt < 8; nt++) {
                    asm volatile(
                        "mma.sync.aligned.m16n8k16.row.col.f32.f16.f16.f32 "
                        "{%0,%1,%2,%3}, {%4,%5,%6,%7}, {%8,%9}, {%0,%1,%2,%3};\n"
                        : "+f"(acc[mt][nt][0]), "+f"(acc[mt][nt][1]),
                          "+f"(acc[mt][nt][2]), "+f"(acc[mt][nt][3])
                        : "r"(af[mt][0]), "r"(af[mt][1]), "r"(af[mt][2]), "r"(af[mt][3]),
                          "r"(bf[nt][0]), "r"(bf[nt][1]));
                }
        }

        if (kt + 2 < KT) loadTile(kt + 2, (kt + 2) % STAGES);
        cp_commit();
    }

    // Epilogue
#pragma unroll
    for (int mt = 0; mt < 2; mt++) {
#pragma unroll
        for (int nt = 0; nt < 8; nt++) {
            int row0 = m0 + wm * 32 + mt * 16 + g;
            int col  = n0 + wn * 64 + nt * 8 + 2 * tg;
#pragma unroll
            for (int rr = 0; rr < 2; rr++) {
                int row = row0 + rr * 8;
                float v0 = acc[mt][nt][rr * 2 + 0];
                float v1 = acc[mt][nt][rr * 2 + 1];
                if (EPI == 1) {
                    v0 = gelu_f(v0 + bias[col]);
                    v1 = gelu_f(v1 + bias[col + 1]);
                } else if (EPI == 2) {
                    float2 rv = *reinterpret_cast<const float2*>(&Res[(size_t)row * ldc + col]);
                    v0 += rv.x; v1 += rv.y;
                } else if (EPI == 3) {
                    float2 rv = *reinterpret_cast<const float2*>(&Res[(size_t)row * ldc + col]);
                    v0 += bias[col] + rv.x; v1 += bias[col + 1] + rv.y;
                }
                if (OUT == 2) {
                    *reinterpret_cast<__half2*>(&Ch[(size_t)row * ldc + col]) =
                        __floats2half2_rn(v0, v1);
                } else {
                    float2 ov; ov.x = v0; ov.y = v1;
                    *reinterpret_cast<float2*>(&Cf[(size_t)row * ldc + col]) = ov;
                }
            }
        }
    }
}

// ---------------------------------------------------------------------------
// Launch (with capture-safe fork-join: weight transposes overlap dense GEMMs)
// ---------------------------------------------------------------------------
extern "C" void kernel_launch(void* const* d_in, const int* in_sizes, int n_in,
                              void* d_out, int out_size)
{
    (void)in_sizes; (void)n_in; (void)out_size;
    const float* x     = (const float*)d_in[0];
    const float* lns   = (const float*)d_in[1];
    const float* lno   = (const float*)d_in[2];
    const float* wq    = (const float*)d_in[3];
    const float* wk    = (const float*)d_in[4];
    const float* wv    = (const float*)d_in[5];
    const float* wo    = (const float*)d_in[6];
    const float* w_in  = (const float*)d_in[7];
    const float* b_in  = (const float*)d_in[8];
    const float* w_out = (const float*)d_in[9];
    const float* b_out = (const float*)d_in[10];
    float* out = (float*)d_out;

    __half *xn, *xn2, *q, *k, *v, *vt, *ctx, *hbuf, *p, *sc, *wh;
    float *x2;
    cudaGetSymbolAddress((void**)&xn,   g_xn);
    cudaGetSymbolAddress((void**)&xn2,  g_xn2);
    cudaGetSymbolAddress((void**)&q,    g_q);
    cudaGetSymbolAddress((void**)&k,    g_k);
    cudaGetSymbolAddress((void**)&v,    g_v);
    cudaGetSymbolAddress((void**)&vt,   g_vt);
    cudaGetSymbolAddress((void**)&ctx,  g_ctx);
    cudaGetSymbolAddress((void**)&hbuf, g_h);
    cudaGetSymbolAddress((void**)&p,    g_p);
    cudaGetSymbolAddress((void**)&sc,   g_sc);
    cudaGetSymbolAddress((void**)&wh,   g_wh);
    cudaGetSymbolAddress((void**)&x2,   g_x2);

    const size_t WSZ = (size_t)D_MODEL * D_MODEL;
    __half* wqT  = wh;
    __half* wkT  = wh + WSZ;
    __half* wvT  = wh + 2 * WSZ;
    __half* woT  = wh + 3 * WSZ;
    __half* winT = wh + 4 * WSZ;                    // [D_FF, D_MODEL]
    __half* wouT = winT + (size_t)D_MODEL * D_FF;   // [D_MODEL, D_FF]

    cudaFuncSetAttribute(gemm_h<0,2,false,false>, cudaFuncAttributeMaxDynamicSharedMemorySize, SMH);
    cudaFuncSetAttribute(gemm_h<0,2,true ,false>, cudaFuncAttributeMaxDynamicSharedMemorySize, SMH);
    cudaFuncSetAttribute(gemm_h<0,2,false,true >, cudaFuncAttributeMaxDynamicSharedMemorySize, SMH);
    cudaFuncSetAttribute(gemm_h<2,0,false,false>, cudaFuncAttributeMaxDynamicSharedMemorySize, SMH);
    cudaFuncSetAttribute(gemm_h<1,2,false,false>, cudaFuncAttributeMaxDynamicSharedMemorySize, SMH);
    cudaFuncSetAttribute(gemm_h<3,0,false,false>, cudaFuncAttributeMaxDynamicSharedMemorySize, SMH);

    // One-time host-side stream/event objects (no device allocation involved).
    static bool s_init = false;
    static cudaStream_t s_side;
    static cudaEvent_t evRoot, evW4, evWJoin, evV, evVJoin;
    if (!s_init) {
        cudaStreamCreateWithFlags(&s_side, cudaStreamNonBlocking);
        cudaEventCreateWithFlags(&evRoot,  cudaEventDisableTiming);
        cudaEventCreateWithFlags(&evW4,    cudaEventDisableTiming);
        cudaEventCreateWithFlags(&evWJoin, cudaEventDisableTiming);
        cudaEventCreateWithFlags(&evV,     cudaEventDisableTiming);
        cudaEventCreateWithFlags(&evVJoin, cudaEventDisableTiming);
        s_init = true;
    }

    dim3 tb(32, 8);

    // Fork: side stream does all weight transposes while main stream computes.
    cudaEventRecord(evRoot, 0);
    cudaStreamWaitEvent(s_side, evRoot, 0);

    // side: QKV/WO weight transpose first (needed soonest), then MLP weights
    transpose4_kernel<<<dim3(128, 128, 4), tb, 0, s_side>>>(wq, wk, wv, wo, wqT, wkT, wvT, woT);
    cudaEventRecord(evW4, s_side);
    transpose_rc_kernel<<<dim3(D_FF / 32, D_MODEL / 32), tb, 0, s_side>>>(w_in,  winT, D_MODEL, D_FF);
    transpose_rc_kernel<<<dim3(D_MODEL / 32, D_FF / 32), tb, 0, s_side>>>(w_out, wouT, D_FF, D_MODEL);
    cudaEventRecord(evWJoin, s_side);

    // main: LayerNorm overlaps transpose4
    layernorm_kernel<<<NROWS, 256>>>(x, lns, lno, xn);

    // main: QKV needs wqT/wkT/wvT/woT
    cudaStreamWaitEvent(0, evW4, 0);
    dim3 gP(D_MODEL / 128, NROWS / 128, 1);
    gemm_h<0,2,false,false><<<gP, 256, SMH>>>(xn, wqT, q, nullptr, nullptr,
        D_MODEL, D_MODEL, D_MODEL, D_MODEL, 0, 0, 0, 0, 0, 0, 1);
    gemm_h<0,2,false,false><<<gP, 256, SMH>>>(xn, wkT, k, nullptr, nullptr,
        D_MODEL, D_MODEL, D_MODEL, D_MODEL, 0, 0, 0, 0, 0, 0, 1);
    gemm_h<0,2,false,false><<<gP, 256, SMH>>>(xn, wvT, v, nullptr, nullptr,
        D_MODEL, D_MODEL, D_MODEL, D_MODEL, 0, 0, 0, 0, 0, 0, 1);

    // fork: V^T transpose on side stream, overlapping RoPE/scores/softmax
    cudaEventRecord(evV, 0);
    cudaStreamWaitEvent(s_side, evV, 0);
    transpose_v_kernel<<<dim3(D_MODEL / 32, NROWS / 32), tb, 0, s_side>>>(v, vt);
    cudaEventRecord(evVJoin, s_side);

    // main: RoPE (q,k only)
    {
        int total = NROWS * N_HEADS * (ROTARY / 2);
        rope_kernel<<<(total + 255) / 256, 256>>>(q, k);
    }

    // main: scores = q @ k^T (causal tile-skip; C fp16)
    dim3 gS(SEQ / 128, SEQ / 128, BATCH * N_HEADS);
    gemm_h<0,2,true ,false><<<gS, 256, SMH>>>(q, k, sc, nullptr, nullptr,
        D_HEAD, D_MODEL, D_MODEL, SEQ,
        (long)SEQ * D_MODEL, (long)D_HEAD,
        (long)SEQ * D_MODEL, (long)D_HEAD,
        (long)N_HEADS * SEQ * SEQ, (long)SEQ * SEQ, N_HEADS);

    // main: causal softmax (fp16 -> fp16)
    softmax_kernel<<<BATCH * N_HEADS * SEQ, 256>>>(sc, p);

    // join V^T, then ctx = probs @ Vt^T (causal K-trunc; C fp16)
    cudaStreamWaitEvent(0, evVJoin, 0);
    dim3 gC(D_HEAD / 128, SEQ / 128, BATCH * N_HEADS);
    gemm_h<0,2,false,true ><<<gC, 256, SMH>>>(p, vt, ctx, nullptr, nullptr,
        SEQ, SEQ, SEQ, D_MODEL,
        (long)N_HEADS * SEQ * SEQ, (long)SEQ * SEQ,
        (long)N_HEADS * D_HEAD * SEQ, (long)D_HEAD * SEQ,
        (long)SEQ * D_MODEL, (long)D_HEAD, N_HEADS);

    // main: x2 = x + ctx @ wo (C fp32)
    gemm_h<2,0,false,false><<<gP, 256, SMH>>>(ctx, woT, x2, nullptr, x,
        D_MODEL, D_MODEL, D_MODEL, D_MODEL, 0, 0, 0, 0, 0, 0, 1);

    // main: LayerNorm 2 (emits fp16)
    layernorm_kernel<<<NROWS, 256>>>(x2, lns, lno, xn2);

    // join MLP weights, then MLP
    cudaStreamWaitEvent(0, evWJoin, 0);
    dim3 gF(D_FF / 128, NROWS / 128, 1);
    gemm_h<1,2,false,false><<<gF, 256, SMH>>>(xn2, winT, hbuf, b_in, nullptr,
        D_MODEL, D_MODEL, D_MODEL, D_FF, 0, 0, 0, 0, 0, 0, 1);

    gemm_h<3,0,false,false><<<gP, 256, SMH>>>(hbuf, wouT, out, b_out, x2,
        D_FF, D_FF, D_FF, D_MODEL, 0, 0, 0, 0, 0, 0, 1);
}

// round 16
// speedup vs baseline: 1.0981x; 1.0017x over previous
#include <cuda_runtime.h>
#include <cuda_fp16.h>
#include <cstdint>
#include <math.h>

#define D_MODEL 4096
#define N_HEADS 16
#define D_HEAD  256
#define ROTARY  64
#define D_FF    16384
#define BATCH   2
#define SEQ     2048
#define NROWS   (BATCH*SEQ)   /* 4096 */

#define STAGES 3
/* fp16 GEMM: BK=64 halfs, row stride 72 halfs = 144B (LDSM conflict-free) */
#define ROWB 144
#define STGB (128 * ROWB)          /* per-stage bytes per operand: 18,432 */
#define SMH  (STAGES * 2 * STGB)   /* 110,592 */

// ---------------------------------------------------------------------------
// Scratch (static device globals; no allocation allowed)
// ---------------------------------------------------------------------------
__device__ __align__(16) __half g_xn [(size_t)NROWS * D_MODEL];
__device__ __align__(16) __half g_xn2[(size_t)NROWS * D_MODEL];
__device__ __align__(16) __half g_q  [(size_t)NROWS * D_MODEL];
__device__ __align__(16) __half g_k  [(size_t)NROWS * D_MODEL];
__device__ __align__(16) __half g_v  [(size_t)NROWS * D_MODEL];
__device__ __align__(16) __half g_vt [(size_t)NROWS * D_MODEL];   // per-head V^T
__device__ __align__(16) __half g_ctx[(size_t)NROWS * D_MODEL];
__device__ __align__(16) __half g_h  [(size_t)NROWS * D_FF];
__device__ __align__(16) __half g_p  [(size_t)BATCH * N_HEADS * SEQ * SEQ]; // 256 MB probs
__device__ __align__(16) __half g_sc [(size_t)BATCH * N_HEADS * SEQ * SEQ]; // 256 MB scores / fp32 split-K scratch
__device__ __align__(16) __half g_wh [(size_t)201326592];                   // 384 MB W^T fp16
__device__ __align__(16) float  g_x2 [(size_t)NROWS * D_MODEL];

// ---------------------------------------------------------------------------
// Helpers
// ---------------------------------------------------------------------------
__device__ __forceinline__ float gelu_f(float x) {
    return 0.5f * x * (1.0f + tanhf(0.7978845608028654f * (x + 0.044715f * x * x * x)));
}
__device__ __forceinline__ void cp16(uint32_t dst, const void* src) {
    asm volatile("cp.async.cg.shared.global [%0], [%1], 16;\n" :: "r"(dst), "l"(src));
}
__device__ __forceinline__ void cp_commit() {
    asm volatile("cp.async.commit_group;\n" ::: "memory");
}
__device__ __forceinline__ void cp_wait1() {
    asm volatile("cp.async.wait_group 1;\n" ::: "memory");
}
__device__ __forceinline__ void ldsm4(uint32_t& r0, uint32_t& r1, uint32_t& r2, uint32_t& r3,
                                      uint32_t addr) {
    asm volatile("ldmatrix.sync.aligned.m8n8.x4.shared.b16 {%0,%1,%2,%3}, [%4];"
                 : "=r"(r0), "=r"(r1), "=r"(r2), "=r"(r3) : "r"(addr));
}

// ---------------------------------------------------------------------------
// Weight transpose + fp16 convert: out[c][r] = half(in[r][c])
// ---------------------------------------------------------------------------
__global__ void transpose4_kernel(const float* __restrict__ w0, const float* __restrict__ w1,
                                  const float* __restrict__ w2, const float* __restrict__ w3,
                                  __half* __restrict__ o0, __half* __restrict__ o1,
                                  __half* __restrict__ o2, __half* __restrict__ o3)
{
    __shared__ float tile[32][33];
    const float* in; __half* out;
    switch (blockIdx.z) {
        case 0: in = w0; out = o0; break;
        case 1: in = w1; out = o1; break;
        case 2: in = w2; out = o2; break;
        default: in = w3; out = o3; break;
    }
    int x = blockIdx.x * 32 + threadIdx.x;
    int y = blockIdx.y * 32 + threadIdx.y;
#pragma unroll
    for (int j = 0; j < 32; j += 8)
        tile[threadIdx.y + j][threadIdx.x] = in[(size_t)(y + j) * 4096 + x];
    __syncthreads();
    x = blockIdx.y * 32 + threadIdx.x;
    y = blockIdx.x * 32 + threadIdx.y;
#pragma unroll
    for (int j = 0; j < 32; j += 8)
        out[(size_t)(y + j) * 4096 + x] = __float2half_rn(tile[threadIdx.x][threadIdx.y + j]);
}

__global__ void transpose_rc_kernel(const float* __restrict__ in, __half* __restrict__ out,
                                    int R, int C)
{
    __shared__ float tile[32][33];
    int x = blockIdx.x * 32 + threadIdx.x;
    int y = blockIdx.y * 32 + threadIdx.y;
#pragma unroll
    for (int j = 0; j < 32; j += 8)
        tile[threadIdx.y + j][threadIdx.x] = in[(size_t)(y + j) * C + x];
    __syncthreads();
    x = blockIdx.y * 32 + threadIdx.x;
    y = blockIdx.x * 32 + threadIdx.y;
#pragma unroll
    for (int j = 0; j < 32; j += 8)
        out[(size_t)(y + j) * R + x] = __float2half_rn(tile[threadIdx.x][threadIdx.y + j]);
}

// V [bt][h*256+d] fp16  ->  Vt [(b*4096 + h*256 + d)][s] fp16 (k-contiguous per head)
__global__ void transpose_v_kernel(const __half* __restrict__ in, __half* __restrict__ out)
{
    __shared__ __half tile[32][33];
    int x = blockIdx.x * 32 + threadIdx.x;    // dmodel col
    int y = blockIdx.y * 32 + threadIdx.y;    // bt row
#pragma unroll
    for (int j = 0; j < 32; j += 8)
        tile[threadIdx.y + j][threadIdx.x] = in[(size_t)(y + j) * D_MODEL + x];
    __syncthreads();
    int d0 = blockIdx.x * 32 + threadIdx.y;   // dmodel index base
    int yo = blockIdx.y * 32 + threadIdx.x;   // bt index
    int b = yo >> 11, s = yo & (SEQ - 1);
#pragma unroll
    for (int j = 0; j < 32; j += 8) {
        int d = d0 + j;
        out[((size_t)(b * D_MODEL + d)) * SEQ + s] = tile[threadIdx.x][threadIdx.y + j];
    }
}

// ---------------------------------------------------------------------------
// LayerNorm: one block per row; emits fp16
// ---------------------------------------------------------------------------
__global__ void layernorm_kernel(const float* __restrict__ x,
                                 const float* __restrict__ scale,
                                 const float* __restrict__ offset,
                                 __half* __restrict__ out)
{
    int row = blockIdx.x;
    const float4* xr = reinterpret_cast<const float4*>(x + (size_t)row * D_MODEL);
    float4 vals[4];
    float s = 0.f, sq = 0.f;
#pragma unroll
    for (int p = 0; p < 4; p++) {
        float4 v = xr[threadIdx.x + p * 256];
        vals[p] = v;
        s  += v.x + v.y + v.z + v.w;
        sq += v.x*v.x + v.y*v.y + v.z*v.z + v.w*v.w;
    }
    __shared__ float shm[64];
#pragma unroll
    for (int o = 16; o > 0; o >>= 1) {
        s  += __shfl_xor_sync(0xffffffffu, s,  o);
        sq += __shfl_xor_sync(0xffffffffu, sq, o);
    }
    int w = threadIdx.x >> 5;
    if ((threadIdx.x & 31) == 0) { shm[w] = s; shm[w + 32] = sq; }
    __syncthreads();
    if (threadIdx.x < 32) {
        float a = (threadIdx.x < 8) ? shm[threadIdx.x]      : 0.f;
        float b = (threadIdx.x < 8) ? shm[32 + threadIdx.x] : 0.f;
#pragma unroll
        for (int o = 4; o > 0; o >>= 1) {
            a += __shfl_xor_sync(0xffffffffu, a, o);
            b += __shfl_xor_sync(0xffffffffu, b, o);
        }
        if (threadIdx.x == 0) { shm[0] = a; shm[1] = b; }
    }
    __syncthreads();
    float mean = shm[0] * (1.0f / D_MODEL);
    float var  = shm[1] * (1.0f / D_MODEL) - mean * mean;
    float inv  = rsqrtf(var + 1e-5f);
    const float4* sc4 = reinterpret_cast<const float4*>(scale);
    const float4* of4 = reinterpret_cast<const float4*>(offset);
    __half2* o2 = reinterpret_cast<__half2*>(out + (size_t)row * D_MODEL);
#pragma unroll
    for (int p = 0; p < 4; p++) {
        int i = threadIdx.x + p * 256;
        float4 v = vals[p], g = sc4[i], b = of4[i];
        o2[i * 2]     = __floats2half2_rn((v.x - mean) * inv * g.x + b.x,
                                          (v.y - mean) * inv * g.y + b.y);
        o2[i * 2 + 1] = __floats2half2_rn((v.z - mean) * inv * g.z + b.z,
                                          (v.w - mean) * inv * g.w + b.w);
    }
}

// ---------------------------------------------------------------------------
// RoPE on fp16 q, k (compute fp32, store fp16)
// ---------------------------------------------------------------------------
__global__ void rope_kernel(__half* __restrict__ q, __half* __restrict__ k)
{
    const int HALF = ROTARY / 2;
    int idx = blockIdx.x * blockDim.x + threadIdx.x;
    int total = NROWS * N_HEADS * HALF;
    if (idx >= total) return;
    int i  = idx % HALF;
    int h  = (idx / HALF) % N_HEADS;
    int bt = idx / (HALF * N_HEADS);
    int t  = bt % SEQ;

    float inv_freq = powf(10000.0f, -(float)i / (float)HALF);
    float fr = (float)t * inv_freq;
    float sn, cs;
    sincosf(fr, &sn, &cs);

    size_t base = (size_t)bt * D_MODEL + (size_t)h * D_HEAD + 2 * i;
    __half2* qp = reinterpret_cast<__half2*>(q + base);
    __half2* kp = reinterpret_cast<__half2*>(k + base);
    float2 qv = __half22float2(*qp);
    float2 kv = __half22float2(*kp);
    *qp = __floats2half2_rn(qv.x * cs - qv.y * sn, qv.y * cs + qv.x * sn);
    *kp = __floats2half2_rn(kv.x * cs - kv.y * sn, kv.y * cs + kv.x * sn);
}

// ---------------------------------------------------------------------------
// Causal softmax: fp16 scores -> fp16 probs.  Skips chunks entirely beyond
// the causal bound on BOTH read and write.
// ---------------------------------------------------------------------------
__global__ void softmax_kernel(const __half* __restrict__ scores, __half* __restrict__ probs)
{
    size_t r = blockIdx.x;
    int t = blockIdx.x % SEQ;
    const __half* row = scores + r * SEQ;
    __half* prow = probs + r * SEQ;
    const float sc = 1.0f / 16.0f;
    int bound = ((t >> 7) + 1) << 7;

    float v[8];
    float mx = -1e30f;
#pragma unroll
    for (int j = 0; j < 8; j++) {
        int col = threadIdx.x + j * 256;
        float xv = -1e30f;
        if (j * 256 <= t) {
            float raw = __half2float(row[col]);
            if (col <= t) xv = raw * sc;
        }
        v[j] = xv;
        mx = fmaxf(mx, xv);
    }
    __shared__ float shm[32];
#pragma unroll
    for (int o = 16; o > 0; o >>= 1) mx = fmaxf(mx, __shfl_xor_sync(0xffffffffu, mx, o));
    if ((threadIdx.x & 31) == 0) shm[threadIdx.x >> 5] = mx;
    __syncthreads();
    if (threadIdx.x < 32) {
        float m = (threadIdx.x < 8) ? shm[threadIdx.x] : -1e30f;
#pragma unroll
        for (int o = 4; o > 0; o >>= 1) m = fmaxf(m, __shfl_xor_sync(0xffffffffu, m, o));
        if (threadIdx.x == 0) shm[0] = m;
    }
    __syncthreads();
    mx = shm[0];
    __syncthreads();

    float s = 0.f;
#pragma unroll
    for (int j = 0; j < 8; j++) { float e = expf(v[j] - mx); v[j] = e; s += e; }
#pragma unroll
    for (int o = 16; o > 0; o >>= 1) s += __shfl_xor_sync(0xffffffffu, s, o);
    if ((threadIdx.x & 31) == 0) shm[threadIdx.x >> 5] = s;
    __syncthreads();
    if (threadIdx.x < 32) {
        float a = (threadIdx.x < 8) ? shm[threadIdx.x] : 0.f;
#pragma unroll
        for (int o = 4; o > 0; o >>= 1) a += __shfl_xor_sync(0xffffffffu, a, o);
        if (threadIdx.x == 0) shm[0] = a;
    }
    __syncthreads();
    float inv = 1.0f / shm[0];
#pragma unroll
    for (int j = 0; j < 8; j++) {
        if (j * 256 < bound)
            prow[threadIdx.x + j * 256] = __float2half_rn(v[j] * inv);
    }
}

// ---------------------------------------------------------------------------
// Split-K reduce: out = p0 + p1 + bias + res   (float4 per thread)
// ---------------------------------------------------------------------------
__global__ void reduce2_kernel(const float4* __restrict__ p0, const float4* __restrict__ p1,
                               const float4* __restrict__ bias, const float4* __restrict__ res,
                               float4* __restrict__ out)
{
    int i = blockIdx.x * blockDim.x + threadIdx.x;   // < NROWS*D_MODEL/4
    float4 a = p0[i], b = p1[i], r = res[i], bb = bias[i & 1023];
    float4 o;
    o.x = a.x + b.x + bb.x + r.x;
    o.y = a.y + b.y + bb.y + r.y;
    o.z = a.z + b.z + bb.z + r.z;
    o.w = a.w + b.w + bb.w + r.w;
    out[i] = o;
}

// ---------------------------------------------------------------------------
// FP16 tensor-core GEMM: C[M,N] = A[M,K] @ Bt[N,K]^T (+epi)
//   128x128 CTA tile, __launch_bounds__(256,2) -> 2 CTAs/SM (16 warps).
//   m16n8k16 MMA via ldmatrix.b16; cp.async 3-stage, BK=64 halfs.
//   EPI: 0 none | 1 bias+gelu | 2 +Res | 3 bias+Res
//   OUT: 0 f32 | 2 fp16
//   CSKIP: causal tile skip.  CKT: causal K truncation.
//   SPLIT3: route n-thirds of a merged-QKV launch to Cv/Cv2/Cv3 (ldc=D_MODEL).
// ---------------------------------------------------------------------------
template<int EPI, int OUT, bool CSKIP, bool CKT, bool SPLIT3>
__global__ void __launch_bounds__(256, 2)
gemm_h(const __half* __restrict__ A, const __half* __restrict__ Bt,
       void* __restrict__ Cv, const float* __restrict__ bias,
       const float* __restrict__ Res,
       int K, int lda, int ldb, int ldc,
       long sAb, long sAh, long sBb, long sBh, long sCb, long sCh, int Hb,
       void* __restrict__ Cv2, void* __restrict__ Cv3)
{
    int m0 = blockIdx.y * 128;
    int n0 = blockIdx.x * 128;
    if (CSKIP) { if (n0 > m0 + 127) return; }

    int z = blockIdx.z;
    int b = z / Hb, hh = z % Hb;
    A  += (size_t)b * sAb + (size_t)hh * sAh;
    Bt += (size_t)b * sBb + (size_t)hh * sBh;
    float*  Cf = reinterpret_cast<float*>(Cv)  + (size_t)b * sCb + (size_t)hh * sCh;
    __half* Ch = reinterpret_cast<__half*>(Cv) + (size_t)b * sCb + (size_t)hh * sCh;

    int colbase = n0;
    if (SPLIT3) {
        int third = n0 >> 12;                 // 0:q 1:k 2:v
        colbase = n0 & 4095;
        Ch = (third == 0) ? reinterpret_cast<__half*>(Cv)
           : (third == 1) ? reinterpret_cast<__half*>(Cv2)
                          : reinterpret_cast<__half*>(Cv3);
    }

    extern __shared__ char smem_dyn[];
    uint32_t aBase = (uint32_t)__cvta_generic_to_shared(smem_dyn);
    uint32_t bBase = aBase + STAGES * STGB;

    int tid = threadIdx.x;
    int lane = tid & 31, warp = tid >> 5;
    int wm = warp & 3, wn = warp >> 2;
    int g  = lane >> 2, tg = lane & 3;

    float acc[2][8][4] = {};

    int KT = K >> 6;
    if (CKT) { int lim = (m0 + 128) >> 6; if (lim < KT) KT = lim; }

    int lc = tid & 7, lr = tid >> 3;

    auto loadTile = [&](int kt, int s) {
        const __half* ap = A + (size_t)m0 * lda + (size_t)kt * 64;
#pragma unroll
        for (int p = 0; p < 4; p++) {
            int row = lr + p * 32;
            cp16(aBase + (uint32_t)(s * STGB + row * ROWB + lc * 16),
                 ap + (size_t)row * lda + lc * 8);
        }
        const __half* bp = Bt + (size_t)n0 * ldb + (size_t)kt * 64;
#pragma unroll
        for (int p = 0; p < 4; p++) {
            int row = lr + p * 32;
            cp16(bBase + (uint32_t)(s * STGB + row * ROWB + lc * 16),
                 bp + (size_t)row * ldb + lc * 8);
        }
    };

    loadTile(0, 0); cp_commit();
    if (KT > 1) loadTile(1, 1);
    cp_commit();

    int lane_row = (lane & 7) | (((lane >> 3) & 1) << 3);
    int lane_kb  = (lane >> 4) << 4;
    uint32_t aoff0 = (uint32_t)((wm * 32 + lane_row) * ROWB + lane_kb);
    uint32_t boff0 = (uint32_t)((wn * 64 + lane_row) * ROWB + lane_kb);

    for (int kt = 0; kt < KT; kt++) {
        cp_wait1();
        __syncthreads();
        int s = kt % STAGES;
        uint32_t aS = aBase + (uint32_t)(s * STGB) + aoff0;
        uint32_t bS = bBase + (uint32_t)(s * STGB) + boff0;

#pragma unroll
        for (int kk = 0; kk < 4; kk++) {
            uint32_t af[2][4], bf[8][2];
            uint32_t kkb = kk * 32;
#pragma unroll
            for (int mt = 0; mt < 2; mt++)
                ldsm4(af[mt][0], af[mt][1], af[mt][2], af[mt][3],
                      aS + (uint32_t)(mt * 16 * ROWB) + kkb);
#pragma unroll
            for (int p = 0; p < 4; p++)
                ldsm4(bf[2*p][0], bf[2*p+1][0], bf[2*p][1], bf[2*p+1][1],
                      bS + (uint32_t)(p * 16 * ROWB) + kkb);
#pragma unroll
            for (int mt = 0; mt < 2; mt++)
#pragma unroll
                for (int nt = 0; nt < 8; nt++) {
                    asm volatile(
                        "mma.sync.aligned.m16n8k16.row.col.f32.f16.f16.f32 "
                        "{%0,%1,%2,%3}, {%4,%5,%6,%7}, {%8,%9}, {%0,%1,%2,%3};\n"
                        : "+f"(acc[mt][nt][0]), "+f"(acc[mt][nt][1]),
                          "+f"(acc[mt][nt][2]), "+f"(acc[mt][nt][3])
                        : "r"(af[mt][0]), "r"(af[mt][1]), "r"(af[mt][2]), "r"(af[mt][3]),
                          "r"(bf[nt][0]), "r"(bf[nt][1]));
                }
        }

        if (kt + 2 < KT) loadTile(kt + 2, (kt + 2) % STAGES);
        cp_commit();
    }

    // Epilogue
#pragma unroll
    for (int mt = 0; mt < 2; mt++) {
#pragma unroll
        for (int nt = 0; nt < 8; nt++) {
            int row0 = m0 + wm * 32 + mt * 16 + g;
            int col  = colbase + wn * 64 + nt * 8 + 2 * tg;
#pragma unroll
            for (int rr = 0; rr < 2; rr++) {
                int row = row0 + rr * 8;
                float v0 = acc[mt][nt][rr * 2 + 0];
                float v1 = acc[mt][nt][rr * 2 + 1];
                if (EPI == 1) {
                    v0 = gelu_f(v0 + bias[col]);
                    v1 = gelu_f(v1 + bias[col + 1]);
                } else if (EPI == 2) {
                    float2 rv = *reinterpret_cast<const float2*>(&Res[(size_t)row * ldc + col]);
                    v0 += rv.x; v1 += rv.y;
                } else if (EPI == 3) {
                    float2 rv = *reinterpret_cast<const float2*>(&Res[(size_t)row * ldc + col]);
                    v0 += bias[col] + rv.x; v1 += bias[col + 1] + rv.y;
                }
                if (OUT == 2) {
                    *reinterpret_cast<__half2*>(&Ch[(size_t)row * ldc + col]) =
                        __floats2half2_rn(v0, v1);
                } else {
                    float2 ov; ov.x = v0; ov.y = v1;
                    *reinterpret_cast<float2*>(&Cf[(size_t)row * ldc + col]) = ov;
                }
            }
        }
    }
}

// ---------------------------------------------------------------------------
// Launch (capture-safe fork-join; merged QKV; split-K MLP2)
// ---------------------------------------------------------------------------
extern "C" void kernel_launch(void* const* d_in, const int* in_sizes, int n_in,
                              void* d_out, int out_size)
{
    (void)in_sizes; (void)n_in; (void)out_size;
    const float* x     = (const float*)d_in[0];
    const float* lns   = (const float*)d_in[1];
    const float* lno   = (const float*)d_in[2];
    const float* wq    = (const float*)d_in[3];
    const float* wk    = (const float*)d_in[4];
    const float* wv    = (const float*)d_in[5];
    const float* wo    = (const float*)d_in[6];
    const float* w_in  = (const float*)d_in[7];
    const float* b_in  = (const float*)d_in[8];
    const float* w_out = (const float*)d_in[9];
    const float* b_out = (const float*)d_in[10];
    float* out = (float*)d_out;

    __half *xn, *xn2, *q, *k, *v, *vt, *ctx, *hbuf, *p, *sc, *wh;
    float *x2;
    cudaGetSymbolAddress((void**)&xn,   g_xn);
    cudaGetSymbolAddress((void**)&xn2,  g_xn2);
    cudaGetSymbolAddress((void**)&q,    g_q);
    cudaGetSymbolAddress((void**)&k,    g_k);
    cudaGetSymbolAddress((void**)&v,    g_v);
    cudaGetSymbolAddress((void**)&vt,   g_vt);
    cudaGetSymbolAddress((void**)&ctx,  g_ctx);
    cudaGetSymbolAddress((void**)&hbuf, g_h);
    cudaGetSymbolAddress((void**)&p,    g_p);
    cudaGetSymbolAddress((void**)&sc,   g_sc);
    cudaGetSymbolAddress((void**)&wh,   g_wh);
    cudaGetSymbolAddress((void**)&x2,   g_x2);

    const size_t WSZ = (size_t)D_MODEL * D_MODEL;
    __half* wqT  = wh;                              // packed rows 0-4095
    __half* wkT  = wh + WSZ;                        // rows 4096-8191
    __half* wvT  = wh + 2 * WSZ;                    // rows 8192-12287
    __half* woT  = wh + 3 * WSZ;
    __half* winT = wh + 4 * WSZ;                    // [D_FF, D_MODEL]
    __half* wouT = winT + (size_t)D_MODEL * D_FF;   // [D_MODEL, D_FF]

    cudaFuncSetAttribute(gemm_h<0,2,false,false,true >, cudaFuncAttributeMaxDynamicSharedMemorySize, SMH);
    cudaFuncSetAttribute(gemm_h<0,2,true ,false,false>, cudaFuncAttributeMaxDynamicSharedMemorySize, SMH);
    cudaFuncSetAttribute(gemm_h<0,2,false,true ,false>, cudaFuncAttributeMaxDynamicSharedMemorySize, SMH);
    cudaFuncSetAttribute(gemm_h<2,0,false,false,false>, cudaFuncAttributeMaxDynamicSharedMemorySize, SMH);
    cudaFuncSetAttribute(gemm_h<1,2,false,false,false>, cudaFuncAttributeMaxDynamicSharedMemorySize, SMH);
    cudaFuncSetAttribute(gemm_h<0,0,false,false,false>, cudaFuncAttributeMaxDynamicSharedMemorySize, SMH);

    // One-time host-side stream/event objects (no device allocation involved).
    static bool s_init = false;
    static cudaStream_t s_side;
    static cudaEvent_t evRoot, evW4, evWJoin, evV, evVJoin;
    if (!s_init) {
        cudaStreamCreateWithFlags(&s_side, cudaStreamNonBlocking);
        cudaEventCreateWithFlags(&evRoot,  cudaEventDisableTiming);
        cudaEventCreateWithFlags(&evW4,    cudaEventDisableTiming);
        cudaEventCreateWithFlags(&evWJoin, cudaEventDisableTiming);
        cudaEventCreateWithFlags(&evV,     cudaEventDisableTiming);
        cudaEventCreateWithFlags(&evVJoin, cudaEventDisableTiming);
        s_init = true;
    }

    dim3 tb(32, 8);

    // Fork: side stream does all weight transposes while main stream computes.
    cudaEventRecord(evRoot, 0);
    cudaStreamWaitEvent(s_side, evRoot, 0);

    transpose4_kernel<<<dim3(128, 128, 4), tb, 0, s_side>>>(wq, wk, wv, wo, wqT, wkT, wvT, woT);
    cudaEventRecord(evW4, s_side);
    transpose_rc_kernel<<<dim3(D_FF / 32, D_MODEL / 32), tb, 0, s_side>>>(w_in,  winT, D_MODEL, D_FF);
    transpose_rc_kernel<<<dim3(D_MODEL / 32, D_FF / 32), tb, 0, s_side>>>(w_out, wouT, D_FF, D_MODEL);
    cudaEventRecord(evWJoin, s_side);

    // main: LayerNorm overlaps transpose4
    layernorm_kernel<<<NROWS, 256>>>(x, lns, lno, xn);

    // main: merged QKV (ONE launch, packed weights; outputs routed to q/k/v)
    cudaStreamWaitEvent(0, evW4, 0);
    dim3 gQ(3 * D_MODEL / 128, NROWS / 128, 1);
    gemm_h<0,2,false,false,true ><<<gQ, 256, SMH>>>(xn, wh, q, nullptr, nullptr,
        D_MODEL, D_MODEL, D_MODEL, D_MODEL, 0, 0, 0, 0, 0, 0, 1, k, v);

    // fork: V^T transpose on side stream, overlapping RoPE/scores/softmax
    cudaEventRecord(evV, 0);
    cudaStreamWaitEvent(s_side, evV, 0);
    transpose_v_kernel<<<dim3(D_MODEL / 32, NROWS / 32), tb, 0, s_side>>>(v, vt);
    cudaEventRecord(evVJoin, s_side);

    // main: RoPE (q,k)
    {
        int total = NROWS * N_HEADS * (ROTARY / 2);
        rope_kernel<<<(total + 255) / 256, 256>>>(q, k);
    }

    // main: scores = q @ k^T (causal tile-skip; C fp16)
    dim3 gS(SEQ / 128, SEQ / 128, BATCH * N_HEADS);
    gemm_h<0,2,true ,false,false><<<gS, 256, SMH>>>(q, k, sc, nullptr, nullptr,
        D_HEAD, D_MODEL, D_MODEL, SEQ,
        (long)SEQ * D_MODEL, (long)D_HEAD,
        (long)SEQ * D_MODEL, (long)D_HEAD,
        (long)N_HEADS * SEQ * SEQ, (long)SEQ * SEQ, N_HEADS, nullptr, nullptr);

    // main: causal softmax (fp16 -> fp16)
    softmax_kernel<<<BATCH * N_HEADS * SEQ, 256>>>(sc, p);

    // join V^T, then ctx = probs @ Vt^T (causal K-trunc; C fp16)
    cudaStreamWaitEvent(0, evVJoin, 0);
    dim3 gC(D_HEAD / 128, SEQ / 128, BATCH * N_HEADS);
    gemm_h<0,2,false,true ,false><<<gC, 256, SMH>>>(p, vt, ctx, nullptr, nullptr,
        SEQ, SEQ, SEQ, D_MODEL,
        (long)N_HEADS * SEQ * SEQ, (long)SEQ * SEQ,
        (long)N_HEADS * D_HEAD * SEQ, (long)D_HEAD * SEQ,
        (long)SEQ * D_MODEL, (long)D_HEAD, N_HEADS, nullptr, nullptr);

    // main: x2 = x + ctx @ wo (C fp32)
    dim3 gP(D_MODEL / 128, NROWS / 128, 1);
    gemm_h<2,0,false,false,false><<<gP, 256, SMH>>>(ctx, woT, x2, nullptr, x,
        D_MODEL, D_MODEL, D_MODEL, D_MODEL, 0, 0, 0, 0, 0, 0, 1, nullptr, nullptr);

    // main: LayerNorm 2 (emits fp16)
    layernorm_kernel<<<NROWS, 256>>>(x2, lns, lno, xn2);

    // join MLP weights, then MLP1
    cudaStreamWaitEvent(0, evWJoin, 0);
    dim3 gF(D_FF / 128, NROWS / 128, 1);
    gemm_h<1,2,false,false,false><<<gF, 256, SMH>>>(xn2, winT, hbuf, b_in, nullptr,
        D_MODEL, D_MODEL, D_MODEL, D_FF, 0, 0, 0, 0, 0, 0, 1, nullptr, nullptr);

    // MLP2 as split-K=2 in ONE launch (z = K-half), fp32 partials in sc scratch
    float* pk = reinterpret_cast<float*>(sc);       // 2 x 67 MB partials (scores retired)
    dim3 g2(D_MODEL / 128, NROWS / 128, 2);
    gemm_h<0,0,false,false,false><<<g2, 256, SMH>>>(hbuf, wouT, pk, nullptr, nullptr,
        D_FF / 2, D_FF, D_FF, D_MODEL,
        (long)(D_FF / 2), 0, (long)(D_FF / 2), 0,
        (long)NROWS * D_MODEL, 0, 1, nullptr, nullptr);

    // out = p0 + p1 + b_out + x2
    reduce2_kernel<<<(NROWS * D_MODEL / 4) / 256, 256>>>(
        reinterpret_cast<const float4*>(pk),
        reinterpret_cast<const float4*>(pk + (size_t)NROWS * D_MODEL),
        reinterpret_cast<const float4*>(b_out),
        reinterpret_cast<const float4*>(x2),
        reinterpret_cast<float4*>(out));
}